// round 13
// baseline (speedup 1.0000x reference)
#include <cuda_runtime.h>
#include <cuda_fp16.h>
#include <math.h>
#include <cstdint>

// Problem constants
#define BATCH 2
#define SEQ   2048
#define DMODEL 1024
#define NHEADS 16
#define NKV    4
#define HDIM   64
#define ROWS   (BATCH * SEQ)          // 4096
#define DKV    (NKV * HDIM)           // 256
#define KDIM   1024
#define NQKV   (DMODEL + 2 * DKV)     // 1536

// ---------------- scratch (static __device__, no allocation) ----------------
__device__ __half g_xhi[ROWS * DMODEL];     // x split; reused for attn out
__device__ __half g_xlo[ROWS * DMODEL];
__device__ __half g_Qhi[ROWS * DMODEL];
__device__ __half g_Qlo[ROWS * DMODEL];
__device__ __half g_Khi[ROWS * DKV];
__device__ __half g_Klo[ROWS * DKV];
__device__ __half g_Vhi[ROWS * DKV];
__device__ __half g_wqkv[NQKV * KDIM];      // transposed [N,K], fp16 (hi only)
__device__ __half g_wo[DMODEL * KDIM];
__device__ float2 g_rope[SEQ * 32];         // (cos, sin) per (s, j)

__device__ __forceinline__ uint32_t smem_u32(const void* p) {
    uint32_t a;
    asm("{ .reg .u64 t; cvta.to.shared.u64 t, %1; cvt.u32.u64 %0, t; }"
        : "=r"(a) : "l"(p));
    return a;
}
#define SMEM_SWIZZLE_128B(off) ((off) ^ (((off) >> 3) & 0x70))
#define SMEM_SWIZZLE_64B(off)  ((off) ^ (((off) >> 3) & 0x30))

__device__ __forceinline__ void ldsm_x4(uint32_t& r0, uint32_t& r1,
                                        uint32_t& r2, uint32_t& r3,
                                        uint32_t addr) {
    asm volatile("ldmatrix.sync.aligned.m8n8.x4.shared.b16 {%0,%1,%2,%3}, [%4];"
                 : "=r"(r0), "=r"(r1), "=r"(r2), "=r"(r3) : "r"(addr));
}
__device__ __forceinline__ void ldsm_x4_t(uint32_t& r0, uint32_t& r1,
                                          uint32_t& r2, uint32_t& r3,
                                          uint32_t addr) {
    asm volatile("ldmatrix.sync.aligned.m8n8.x4.trans.shared.b16 {%0,%1,%2,%3}, [%4];"
                 : "=r"(r0), "=r"(r1), "=r"(r2), "=r"(r3) : "r"(addr));
}
__device__ __forceinline__ void mma16816(float* c, const uint32_t* a,
                                         const uint32_t* b) {
    asm volatile(
        "mma.sync.aligned.m16n8k16.row.col.f32.f16.f16.f32 "
        "{%0,%1,%2,%3}, {%4,%5,%6,%7}, {%8,%9}, {%0,%1,%2,%3};"
        : "+f"(c[0]), "+f"(c[1]), "+f"(c[2]), "+f"(c[3])
        : "r"(a[0]), "r"(a[1]), "r"(a[2]), "r"(a[3]), "r"(b[0]), "r"(b[1]));
}
__device__ __forceinline__ uint32_t packhf(float lo, float hi) {
    __half2 t = __floats2half2_rn(lo, hi);   // .x -> low 16 bits
    return *reinterpret_cast<uint32_t*>(&t);
}
__device__ __forceinline__ float hres(float c) {
    return c - __half2float(__float2half_rn(c));
}
__device__ __forceinline__ void cp16(uint32_t s, const void* g) {
    asm volatile("cp.async.cg.shared.global [%0], [%1], 16;" :: "r"(s), "l"(g));
}
#define CP_COMMIT() asm volatile("cp.async.commit_group;")
#define CP_WAIT(n)  asm volatile("cp.async.wait_group %0;" :: "n"(n))

// ---------------- fused prep: x split + 4 weight transposes + rope table -----
__global__ void prep_kernel(const float* __restrict__ x,
                            const float* __restrict__ Wq,
                            const float* __restrict__ Wk,
                            const float* __restrict__ Wv,
                            const float* __restrict__ Wo,
                            const int* __restrict__ offset_ptr,
                            __half* __restrict__ xhi,
                            __half* __restrict__ xlo,
                            __half* __restrict__ wqkv,
                            __half* __restrict__ wo,
                            float2* __restrict__ ropeTab) {
    const int z = blockIdx.z;
    const int tx = threadIdx.x, ty = threadIdx.y;

    if (z == 4) {   // split x
        int i = (blockIdx.y * 128 + blockIdx.x) * 256 + ty * 32 + tx;
        float4 v = reinterpret_cast<const float4*>(x)[i];
        uint32_t* hp = reinterpret_cast<uint32_t*>(xhi) + 2 * i;
        uint32_t* lp = reinterpret_cast<uint32_t*>(xlo) + 2 * i;
        hp[0] = packhf(v.x, v.y); hp[1] = packhf(v.z, v.w);
        lp[0] = packhf(hres(v.x), hres(v.y));
        lp[1] = packhf(hres(v.z), hres(v.w));
        return;
    }
    if (z == 5) {   // rope table: 2048 x 32 entries
        int bid = blockIdx.y * 128 + blockIdx.x;
        if (bid >= 256) return;
        int i = bid * 256 + ty * 32 + tx;      // 0..65535
        int s = i >> 5, j = i & 31;
        float pos = (float)(s + offset_ptr[0]);
        float inv = powf(10000.0f, -(float)j / 32.0f);
        float ang = pos * inv;
        ropeTab[i] = make_float2(cosf(ang), sinf(ang));
        return;
    }

    const float* W;
    __half* hi;
    int N;
    if (z == 0)      { W = Wq; N = DMODEL; hi = wqkv; }
    else if (z == 1) { W = Wk; N = DKV; hi = wqkv + (size_t)DMODEL * KDIM; }
    else if (z == 2) { W = Wv; N = DKV; hi = wqkv + (size_t)(DMODEL + DKV) * KDIM; }
    else             { W = Wo; N = DMODEL; hi = wo; }

    int nb = blockIdx.x * 32;
    if (nb >= N) return;
    int kb = blockIdx.y * 32;

    __shared__ float tile[32][33];
    for (int i = ty; i < 32; i += 8)
        tile[i][tx] = W[(size_t)(kb + i) * N + nb + tx];
    __syncthreads();
    for (int i = ty; i < 32; i += 8) {
        float v = tile[tx][i];
        hi[(size_t)(nb + i) * KDIM + kb + tx] = __float2half_rn(v);
    }
}

// ---------------- shared GEMM mainloop (macro) --------------------------------
// 512 threads, 16 warps in 4m x 4n grid, warp tile 32x32.
// fp16 2-term: C = Ahi*B + Alo*B. 4-stage cp.async pipeline, CHUNK=32
// (64B rows, SW64), 3 chunks in flight -> L2/DRAM latency fully covered.
#define CHUNK 32
#define NCH   (KDIM / CHUNK)          // 32
#define STG_BYTES 24576               // Ahi 8K | Alo 8K | B 8K
#define NSTG  4
#define GEMM_SMEM_BYTES (NSTG * STG_BYTES + 1024)

#define GQ_LOAD_CHUNK(ch_, stg_) do {                                          \
        const int k0_ = (ch_) * CHUNK;                                         \
        uint32_t sb0_ = smem_u32(sm + (stg_) * STG_BYTES);                     \
        int row_ = t >> 2;                                                     \
        int c_ = t & 3;                                                        \
        uint32_t sw_ = SMEM_SWIZZLE_64B((uint32_t)(row_ * 64 + c_ * 16));      \
        size_t ao_ = (size_t)(rowBase + row_) * KDIM + k0_ + c_ * 8;           \
        size_t bo_ = (size_t)(colBase + row_) * KDIM + k0_ + c_ * 8;           \
        cp16(sb0_ + sw_, Ahi + ao_);                                           \
        cp16(sb0_ + 8192 + sw_, Alo + ao_);                                    \
        cp16(sb0_ + 16384 + sw_, Bw + bo_);                                    \
    } while (0)

#define GQ_LOAD_FRAGS(s_) do {                                                 \
        _Pragma("unroll")                                                      \
        for (int mb = 0; mb < 2; mb++) {                                       \
            int row = warp_m * 32 + mb * 16 + a_row;                           \
            uint32_t sw = SMEM_SWIZZLE_64B(                                    \
                (uint32_t)(row * 64 + a_colB + (s_) * 32));                    \
            ldsm_x4(fa_hi[mb][0], fa_hi[mb][1], fa_hi[mb][2], fa_hi[mb][3],    \
                    aHi + sw);                                                 \
            ldsm_x4(fa_lo[mb][0], fa_lo[mb][1], fa_lo[mb][2], fa_lo[mb][3],    \
                    aLo + sw);                                                 \
        }                                                                      \
        _Pragma("unroll")                                                      \
        for (int p = 0; p < 2; p++) {                                          \
            int row = warp_n * 32 + p * 16 + b_rowl;                           \
            uint32_t sw = SMEM_SWIZZLE_64B(                                    \
                (uint32_t)(row * 64 + b_colB + (s_) * 32));                    \
            ldsm_x4(fb[2 * p][0], fb[2 * p][1],                                \
                    fb[2 * p + 1][0], fb[2 * p + 1][1], bW + sw);              \
        }                                                                      \
    } while (0)

#define GQ_MMA() do {                                                          \
        _Pragma("unroll")                                                      \
        for (int nb = 0; nb < 4; nb++)                                         \
            _Pragma("unroll")                                                  \
            for (int mb = 0; mb < 2; mb++)                                     \
                mma16816(acc[mb][nb], fa_hi[mb], fb[nb]);                      \
        _Pragma("unroll")                                                      \
        for (int nb = 0; nb < 4; nb++)                                         \
            _Pragma("unroll")                                                  \
            for (int mb = 0; mb < 2; mb++)                                     \
                mma16816(acc[mb][nb], fa_lo[mb], fb[nb]);                      \
    } while (0)

#define GEMM_MAINLOOP(Ahi, Alo, Bw)                                            \
    uint32_t base = (smem_u32(dsm) + 1023u) & ~1023u;                          \
    char* sm = dsm + (base - smem_u32(dsm));                                   \
    float acc[2][4][4];                                                        \
    _Pragma("unroll")                                                          \
    for (int mb = 0; mb < 2; mb++)                                             \
        _Pragma("unroll")                                                      \
        for (int nb = 0; nb < 4; nb++)                                         \
            _Pragma("unroll")                                                  \
            for (int q = 0; q < 4; q++) acc[mb][nb][q] = 0.f;                  \
    const int a_row = lid & 15;                                                \
    const int a_colB = (lid >> 4) * 16;                                        \
    const int b_rowl = ((lid >> 4) << 3) + (lid & 7);                          \
    const int b_colB = ((lid >> 3) & 1) * 16;                                  \
    uint32_t fa_hi[2][4], fa_lo[2][4];                                         \
    uint32_t fb[4][2];                                                         \
    GQ_LOAD_CHUNK(0, 0);                                                       \
    CP_COMMIT();                                                               \
    GQ_LOAD_CHUNK(1, 1);                                                       \
    CP_COMMIT();                                                               \
    GQ_LOAD_CHUNK(2, 2);                                                       \
    CP_COMMIT();                                                               \
    for (int ch = 0; ch < NCH; ch++) {                                         \
        CP_WAIT(2);                                                            \
        __syncthreads();                                                       \
        uint32_t stg0 = smem_u32(sm + (ch & 3) * STG_BYTES);                   \
        uint32_t aHi = stg0;                                                   \
        uint32_t aLo = stg0 + 8192;                                            \
        uint32_t bW = stg0 + 16384;                                            \
        GQ_LOAD_FRAGS(0);                                                      \
        if (ch + 3 < NCH) GQ_LOAD_CHUNK(ch + 3, (ch + 3) & 3);                 \
        CP_COMMIT();                                                           \
        GQ_MMA();                                                              \
        GQ_LOAD_FRAGS(1);                                                      \
        GQ_MMA();                                                              \
    }

// ---------------- GEMM with plain fp32 epilogue (O projection) ---------------
__global__ __launch_bounds__(512, 1) void gemm_mma3(
    const __half* __restrict__ Ahi, const __half* __restrict__ Alo,
    const __half* __restrict__ Bw,
    float* __restrict__ C, int Ncols) {
    extern __shared__ char dsm[];
    const int t = threadIdx.x;
    const int wid = t >> 5;
    const int lid = t & 31;
    const int warp_m = wid & 3;
    const int warp_n = wid >> 2;
    const int rowBase = blockIdx.y * 128;
    const int colBase = blockIdx.x * 128;

    GEMM_MAINLOOP(Ahi, Alo, Bw)

    const int g = lid >> 2;
    const int q = lid & 3;
#pragma unroll
    for (int mb = 0; mb < 2; mb++) {
#pragma unroll
        for (int nb = 0; nb < 4; nb++) {
            int row = rowBase + warp_m * 32 + mb * 16 + g;
            int col = colBase + warp_n * 32 + nb * 8 + q * 2;
            *reinterpret_cast<float2*>(&C[(size_t)row * Ncols + col]) =
                make_float2(acc[mb][nb][0], acc[mb][nb][1]);
            *reinterpret_cast<float2*>(&C[(size_t)(row + 8) * Ncols + col]) =
                make_float2(acc[mb][nb][2], acc[mb][nb][3]);
        }
    }
}

// ---------------- QKV GEMM with fused RoPE + hi/lo split epilogue ------------
__global__ __launch_bounds__(512, 1) void gemm_qkv(
    const __half* __restrict__ Ahi, const __half* __restrict__ Alo,
    const __half* __restrict__ Bw,
    __half* __restrict__ qhi, __half* __restrict__ qlo,
    __half* __restrict__ khi, __half* __restrict__ klo,
    __half* __restrict__ vhi,
    const float2* __restrict__ ropeTab) {
    extern __shared__ char dsm[];
    const int t = threadIdx.x;
    const int wid = t >> 5;
    const int lid = t & 31;
    const int warp_m = wid & 3;
    const int warp_n = wid >> 2;
    const int rowBase = blockIdx.y * 128;
    const int colBase = blockIdx.x * 128;

    GEMM_MAINLOOP(Ahi, Alo, Bw)

    const int g2 = lid >> 2;
    const int qd2 = (lid & 3) * 2;

    if (colBase >= DMODEL + DKV) {
        // V: plain fp16, direct from registers
        const int cb = colBase - DMODEL - DKV;
#pragma unroll
        for (int mb = 0; mb < 2; mb++) {
            int r0 = rowBase + warp_m * 32 + mb * 16 + g2;
#pragma unroll
            for (int nb = 0; nb < 4; nb++) {
                int col = cb + warp_n * 32 + nb * 8 + qd2;
                size_t o0 = (size_t)r0 * DKV + col;
                size_t o1 = (size_t)(r0 + 8) * DKV + col;
                *reinterpret_cast<uint32_t*>(vhi + o0) =
                    packhf(acc[mb][nb][0], acc[mb][nb][1]);
                *reinterpret_cast<uint32_t*>(vhi + o1) =
                    packhf(acc[mb][nb][2], acc[mb][nb][3]);
            }
        }
        return;
    }

    // Q/K: bounce accumulators through smem for cross-warp RoPE
    float* stile = reinterpret_cast<float*>(sm);   // [128][128] f32, XOR swizzle
    __syncthreads();   // all warps done with final-chunk fragment reads
#pragma unroll
    for (int mb = 0; mb < 2; mb++) {
#pragma unroll
        for (int nb = 0; nb < 4; nb++) {
            int rl0 = warp_m * 32 + mb * 16 + g2;
            int cw = warp_n * 32 + nb * 8 + qd2;
            uint32_t w0 = rl0 * 128 + (cw ^ ((rl0 & 7) << 3));
            uint32_t w1 = (rl0 + 8) * 128 + (cw ^ (((rl0 + 8) & 7) << 3));
            *reinterpret_cast<float2*>(stile + w0) =
                make_float2(acc[mb][nb][0], acc[mb][nb][1]);
            *reinterpret_cast<float2*>(stile + w1) =
                make_float2(acc[mb][nb][2], acc[mb][nb][3]);
        }
    }
    __syncthreads();

    const bool isQ = colBase < DMODEL;
    const float sc = isQ ? 0.125f : 1.0f;   // 1/sqrt(64) folded into Q
    __half* Hhi = isQ ? qhi : khi;
    __half* Hlo = isQ ? qlo : klo;
    const int ncols = isQ ? DMODEL : DKV;
    const int cbase = isQ ? colBase : colBase - DMODEL;

    // 128 rows x 2 heads x 16 j-pairs = 4096 items, 512 threads -> 8 iters
#pragma unroll
    for (int it = 0; it < 8; it++) {
        int i = t + it * 512;
        int j2 = i & 15;
        int head = (i >> 4) & 1;
        int rl = i >> 5;                 // local row 0..127
        int j = 2 * j2;
        int c1 = head * 64 + j;
        uint32_t xr = (uint32_t)((rl & 7) << 3);
        float2 ab0 = *reinterpret_cast<float2*>(stile + rl * 128 + (c1 ^ xr));
        float2 ab1 = *reinterpret_cast<float2*>(stile + rl * 128 + ((c1 + 32) ^ xr));
        int grow = rowBase + rl;
        int srow = grow & (SEQ - 1);
        float2 cs0 = ropeTab[srow * 32 + j];
        float2 cs1 = ropeTab[srow * 32 + j + 1];
        float a0 = ab0.x, a1 = ab0.y, b0 = ab1.x, b1 = ab1.y;
        float q0 = (a0 * cs0.x - b0 * cs0.y) * sc;
        float q1 = (a1 * cs1.x - b1 * cs1.y) * sc;
        float u0 = (b0 * cs0.x + a0 * cs0.y) * sc;
        float u1 = (b1 * cs1.x + a1 * cs1.y) * sc;
        size_t o = (size_t)grow * ncols + cbase + c1;
        *reinterpret_cast<uint32_t*>(Hhi + o) = packhf(q0, q1);
        *reinterpret_cast<uint32_t*>(Hlo + o) = packhf(hres(q0), hres(q1));
        *reinterpret_cast<uint32_t*>(Hhi + o + 32) = packhf(u0, u1);
        *reinterpret_cast<uint32_t*>(Hlo + o + 32) = packhf(hres(u0), hres(u1));
    }
}

// ---------------- tensor-core flash attention (causal, GQA) ------------------
// S = 3-term fp16 (Q hi/lo x K hi/lo), PV = 2-term (P hi/lo x V fp16).
#define KV_STG 24576                  // Khi 8K | Klo 8K | Vhi 8K
#define ATTN2_SMEM (32768 + 2 * KV_STG + 1024)

__global__ __launch_bounds__(256, 1) void attn_mma(
    const __half* __restrict__ Qhi, const __half* __restrict__ Qlo,
    const __half* __restrict__ Khi, const __half* __restrict__ Klo,
    const __half* __restrict__ Vhi,
    __half* __restrict__ Ohi, __half* __restrict__ Olo) {
    extern __shared__ char dsm[];
    uint32_t base = (smem_u32(dsm) + 1023u) & ~1023u;
    char* sm = dsm + (base - smem_u32(dsm));
    char* sQhi = sm;            // 16KB
    char* sQlo = sm + 16384;    // 16KB

    const int qt = (int)gridDim.x - 1 - (int)blockIdx.x;   // heavy CTAs first
    const int h  = blockIdx.y;
    const int b  = blockIdx.z;
    const int hkv = h >> 2;
    const int t  = threadIdx.x;
    const int wid = t >> 5;
    const int lid = t & 31;
    const int g = lid >> 2;
    const int qd = lid & 3;
    const int q0 = qt * 128;

    const size_t kvbase = ((size_t)b * SEQ) * DKV + (size_t)hkv * HDIM;
    const int ntiles = 2 * qt + 2;

#define LOADKV(kt_, stg_) do {                                                  \
        const int k0_ = (kt_) * 64;                                            \
        uint32_t sb0_ = smem_u32(sm + 32768 + (stg_) * KV_STG);                 \
        _Pragma("unroll")                                                       \
        for (int ii = 0; ii < 2; ii++) {                                        \
            int idx_ = t + ii * 256;                                            \
            int row_ = idx_ >> 3;                                               \
            int ch_ = idx_ & 7;                                                 \
            uint32_t sw_ = SMEM_SWIZZLE_128B((uint32_t)(row_ * 128 + ch_ * 16));\
            size_t gl_ = kvbase + (size_t)(k0_ + row_) * DKV + ch_ * 8;         \
            cp16(sb0_ + sw_, Khi + gl_);                                        \
            cp16(sb0_ + 8192 + sw_, Klo + gl_);                                 \
            cp16(sb0_ + 16384 + sw_, Vhi + gl_);                                \
        }                                                                       \
    } while (0)

    // group A: Q hi/lo tiles via cp.async
    {
        const __half* Qh = Qhi + ((size_t)(b * SEQ + q0)) * DMODEL + h * HDIM;
        const __half* Ql = Qlo + ((size_t)(b * SEQ + q0)) * DMODEL + h * HDIM;
#pragma unroll
        for (int ii = 0; ii < 4; ii++) {
            int idx = t + ii * 256;        // 0..1023
            int row = idx >> 3;
            int ch = idx & 7;
            uint32_t sw = SMEM_SWIZZLE_128B((uint32_t)(row * 128 + ch * 16));
            size_t gl = (size_t)row * DMODEL + ch * 8;
            cp16(smem_u32(sQhi) + sw, Qh + gl);
            cp16(smem_u32(sQlo) + sw, Ql + gl);
        }
        CP_COMMIT();
    }
    // group B: KV tile 0
    LOADKV(0, 0);
    CP_COMMIT();

    CP_WAIT(1);        // Q tiles complete
    __syncthreads();

    // ---- Q fragments in registers
    uint32_t qh[4][4], ql[4][4];
    {
        int arow = wid * 16 + (lid & 15);
        int acolB = (lid >> 4) * 16;
#pragma unroll
        for (int s = 0; s < 4; s++) {
            uint32_t sw = SMEM_SWIZZLE_128B((uint32_t)(arow * 128 + acolB + s * 32));
            ldsm_x4(qh[s][0], qh[s][1], qh[s][2], qh[s][3], smem_u32(sQhi) + sw);
            ldsm_x4(ql[s][0], ql[s][1], ql[s][2], ql[s][3], smem_u32(sQlo) + sw);
        }
    }

    float o[8][4];
#pragma unroll
    for (int nb = 0; nb < 8; nb++)
#pragma unroll
        for (int q = 0; q < 4; q++) o[nb][q] = 0.f;
    float m0 = -1e30f, m1 = -1e30f, l0 = 0.f, l1 = 0.f;

    for (int kt = 0; kt < ntiles; kt++) {
        const int k0 = kt * 64;
        if (kt + 1 < ntiles) {
            LOADKV(kt + 1, (kt + 1) & 1);
            CP_COMMIT();
            CP_WAIT(1);
        } else {
            CP_WAIT(0);
        }
        __syncthreads();

        uint32_t kvb = smem_u32(sm + 32768 + (kt & 1) * KV_STG);
        uint32_t sKhi_ = kvb;
        uint32_t sKlo_ = kvb + 8192;
        uint32_t sVhi_ = kvb + 16384;

        // ---- S = Q K^T (3-term fp16, term-major issue)
        float sacc[8][4];
#pragma unroll
        for (int nb = 0; nb < 8; nb++)
#pragma unroll
            for (int q = 0; q < 4; q++) sacc[nb][q] = 0.f;

        {
            int brow = ((lid >> 4) << 3) + (lid & 7);
            int bcolB = ((lid >> 3) & 1) * 16;
#pragma unroll
            for (int s = 0; s < 4; s++) {
                uint32_t kh[8][2], kl[8][2];
#pragma unroll
                for (int p = 0; p < 4; p++) {
                    uint32_t sw = SMEM_SWIZZLE_128B(
                        (uint32_t)((p * 16 + brow) * 128 + bcolB + s * 32));
                    ldsm_x4(kh[2 * p][0], kh[2 * p][1], kh[2 * p + 1][0],
                            kh[2 * p + 1][1], sKhi_ + sw);
                    ldsm_x4(kl[2 * p][0], kl[2 * p][1], kl[2 * p + 1][0],
                            kl[2 * p + 1][1], sKlo_ + sw);
                }
#pragma unroll
                for (int nb = 0; nb < 8; nb++)
                    mma16816(sacc[nb], qh[s], kh[nb]);
#pragma unroll
                for (int nb = 0; nb < 8; nb++)
                    mma16816(sacc[nb], qh[s], kl[nb]);
#pragma unroll
                for (int nb = 0; nb < 8; nb++)
                    mma16816(sacc[nb], ql[s], kh[nb]);
            }
        }

        // ---- causal mask (only diagonal tiles)
        if (kt >= 2 * qt) {
            int rowa = q0 + wid * 16 + g;
#pragma unroll
            for (int nb = 0; nb < 8; nb++) {
                int col = k0 + nb * 8 + qd * 2;
                if (col > rowa)     sacc[nb][0] = -1e30f;
                if (col + 1 > rowa) sacc[nb][1] = -1e30f;
                if (col > rowa + 8)     sacc[nb][2] = -1e30f;
                if (col + 1 > rowa + 8) sacc[nb][3] = -1e30f;
            }
        }

        // ---- online softmax
        {
            float mx0 = -1e30f, mx1 = -1e30f;
#pragma unroll
            for (int nb = 0; nb < 8; nb++) {
                mx0 = fmaxf(mx0, fmaxf(sacc[nb][0], sacc[nb][1]));
                mx1 = fmaxf(mx1, fmaxf(sacc[nb][2], sacc[nb][3]));
            }
            mx0 = fmaxf(mx0, __shfl_xor_sync(0xffffffff, mx0, 1));
            mx0 = fmaxf(mx0, __shfl_xor_sync(0xffffffff, mx0, 2));
            mx1 = fmaxf(mx1, __shfl_xor_sync(0xffffffff, mx1, 1));
            mx1 = fmaxf(mx1, __shfl_xor_sync(0xffffffff, mx1, 2));
            float mn0 = fmaxf(m0, mx0), mn1 = fmaxf(m1, mx1);
            float al0 = __expf(m0 - mn0), al1 = __expf(m1 - mn1);
            m0 = mn0; m1 = mn1;
            l0 *= al0; l1 *= al1;
            float la0 = 0.f, la1 = 0.f;
#pragma unroll
            for (int nb = 0; nb < 8; nb++) {
                sacc[nb][0] = __expf(sacc[nb][0] - mn0);
                sacc[nb][1] = __expf(sacc[nb][1] - mn0);
                sacc[nb][2] = __expf(sacc[nb][2] - mn1);
                sacc[nb][3] = __expf(sacc[nb][3] - mn1);
                la0 += sacc[nb][0] + sacc[nb][1];
                la1 += sacc[nb][2] + sacc[nb][3];
                o[nb][0] *= al0; o[nb][1] *= al0;
                o[nb][2] *= al1; o[nb][3] *= al1;
            }
            l0 += la0; l1 += la1;
        }

        // ---- pack P hi/lo as A-fragments (fp16)
        uint32_t ph[4][4], pl[4][4];
#pragma unroll
        for (int j = 0; j < 4; j++) {
            float* c = sacc[2 * j];
            float* d = sacc[2 * j + 1];
            ph[j][0] = packhf(c[0], c[1]);
            ph[j][1] = packhf(c[2], c[3]);
            ph[j][2] = packhf(d[0], d[1]);
            ph[j][3] = packhf(d[2], d[3]);
            pl[j][0] = packhf(hres(c[0]), hres(c[1]));
            pl[j][1] = packhf(hres(c[2]), hres(c[3]));
            pl[j][2] = packhf(hres(d[0]), hres(d[1]));
            pl[j][3] = packhf(hres(d[2]), hres(d[3]));
        }

        // ---- O += P V (2-term: P hi/lo x V fp16), V via ldmatrix.trans
        {
            int vrow = (lid & 15);
            int vcolB = (lid >> 4) * 16;
#pragma unroll
            for (int j = 0; j < 4; j++) {
                uint32_t vh[8][2];
#pragma unroll
                for (int dj = 0; dj < 4; dj++) {
                    uint32_t sw = SMEM_SWIZZLE_128B(
                        (uint32_t)((j * 16 + vrow) * 128 + dj * 32 + vcolB));
                    ldsm_x4_t(vh[2 * dj][0], vh[2 * dj][1], vh[2 * dj + 1][0],
                              vh[2 * dj + 1][1], sVhi_ + sw);
                }
#pragma unroll
                for (int nb = 0; nb < 8; nb++)
                    mma16816(o[nb], ph[j], vh[nb]);
#pragma unroll
                for (int nb = 0; nb < 8; nb++)
                    mma16816(o[nb], pl[j], vh[nb]);
            }
        }
        __syncthreads();
    }
#undef LOADKV

    // ---- finalize: normalize, write fp16 hi/lo (fused split)
    l0 += __shfl_xor_sync(0xffffffff, l0, 1);
    l0 += __shfl_xor_sync(0xffffffff, l0, 2);
    l1 += __shfl_xor_sync(0xffffffff, l1, 1);
    l1 += __shfl_xor_sync(0xffffffff, l1, 2);
    float inv0 = 1.0f / l0, inv1 = 1.0f / l1;

    int rowa = q0 + wid * 16 + g;
    size_t oa = ((size_t)(b * SEQ + rowa)) * DMODEL + h * HDIM;
    size_t ob = ((size_t)(b * SEQ + rowa + 8)) * DMODEL + h * HDIM;
#pragma unroll
    for (int nb = 0; nb < 8; nb++) {
        int col = nb * 8 + qd * 2;
        float a0 = o[nb][0] * inv0, a1 = o[nb][1] * inv0;
        float b0 = o[nb][2] * inv1, b1 = o[nb][3] * inv1;
        *reinterpret_cast<uint32_t*>(Ohi + oa + col) = packhf(a0, a1);
        *reinterpret_cast<uint32_t*>(Olo + oa + col) = packhf(hres(a0), hres(a1));
        *reinterpret_cast<uint32_t*>(Ohi + ob + col) = packhf(b0, b1);
        *reinterpret_cast<uint32_t*>(Olo + ob + col) = packhf(hres(b0), hres(b1));
    }
}

// ---------------- launch ------------------------------------------------------
extern "C" void kernel_launch(void* const* d_in, const int* in_sizes, int n_in,
                              void* d_out, int out_size) {
    (void)in_sizes; (void)n_in; (void)out_size;
    const float* x  = (const float*)d_in[0];
    const float* Wq = (const float*)d_in[1];
    const float* Wk = (const float*)d_in[2];
    const float* Wv = (const float*)d_in[3];
    const float* Wo = (const float*)d_in[4];
    const int* poff = (const int*)d_in[5];
    float* out = (float*)d_out;

    __half *xhi, *xlo, *qhi, *qlo, *khi, *klo, *vhi, *wqkv, *wo;
    float2* rtab;
    cudaGetSymbolAddress((void**)&xhi, g_xhi);
    cudaGetSymbolAddress((void**)&xlo, g_xlo);
    cudaGetSymbolAddress((void**)&qhi, g_Qhi);
    cudaGetSymbolAddress((void**)&qlo, g_Qlo);
    cudaGetSymbolAddress((void**)&khi, g_Khi);
    cudaGetSymbolAddress((void**)&klo, g_Klo);
    cudaGetSymbolAddress((void**)&vhi, g_Vhi);
    cudaGetSymbolAddress((void**)&wqkv, g_wqkv);
    cudaGetSymbolAddress((void**)&wo, g_wo);
    cudaGetSymbolAddress((void**)&rtab, g_rope);

    cudaFuncSetAttribute(gemm_mma3, cudaFuncAttributeMaxDynamicSharedMemorySize,
                         GEMM_SMEM_BYTES);
    cudaFuncSetAttribute(gemm_qkv, cudaFuncAttributeMaxDynamicSharedMemorySize,
                         GEMM_SMEM_BYTES);
    cudaFuncSetAttribute(attn_mma, cudaFuncAttributeMaxDynamicSharedMemorySize,
                         ATTN2_SMEM);

    // fused prep: x split + weight transposes + rope table (one launch)
    prep_kernel<<<dim3(128, 32, 6), dim3(32, 8)>>>(
        x, Wq, Wk, Wv, Wo, poff, xhi, xlo, wqkv, wo, rtab);

    // fused QKV projection + RoPE + hi/lo quantization (512 thr)
    gemm_qkv<<<dim3(NQKV / 128, ROWS / 128), 512, GEMM_SMEM_BYTES>>>(
        xhi, xlo, wqkv, qhi, qlo, khi, klo, vhi, rtab);

    // attention -> writes hi/lo directly into xhi/xlo
    attn_mma<<<dim3(SEQ / 128, NHEADS, BATCH), 256, ATTN2_SMEM>>>(
        qhi, qlo, khi, klo, vhi, xhi, xlo);

    // O projection (512 thr)
    gemm_mma3<<<dim3(DMODEL / 128, ROWS / 128), 512, GEMM_SMEM_BYTES>>>(
        xhi, xlo, wo, out, DMODEL);
}

// round 14
// speedup vs baseline: 1.1067x; 1.1067x over previous
#include <cuda_runtime.h>
#include <cuda_fp16.h>
#include <math.h>
#include <cstdint>

// Problem constants
#define BATCH 2
#define SEQ   2048
#define DMODEL 1024
#define NHEADS 16
#define NKV    4
#define HDIM   64
#define ROWS   (BATCH * SEQ)          // 4096
#define DKV    (NKV * HDIM)           // 256
#define KDIM   1024
#define NQKV   (DMODEL + 2 * DKV)     // 1536

// ---------------- scratch (static __device__, no allocation) ----------------
__device__ __half g_xhi[ROWS * DMODEL];     // x split; reused for attn out
__device__ __half g_xlo[ROWS * DMODEL];
__device__ __half g_Qhi[ROWS * DMODEL];
__device__ __half g_Qlo[ROWS * DMODEL];
__device__ __half g_Khi[ROWS * DKV];        // K plain fp16 (no residual)
__device__ __half g_Vhi[ROWS * DKV];
__device__ __half g_wqkv[NQKV * KDIM];      // transposed [N,K], fp16
__device__ __half g_wo[DMODEL * KDIM];
__device__ float2 g_rope[SEQ * 32];         // (cos, sin) per (s, j)

__device__ __forceinline__ uint32_t smem_u32(const void* p) {
    uint32_t a;
    asm("{ .reg .u64 t; cvta.to.shared.u64 t, %1; cvt.u32.u64 %0, t; }"
        : "=r"(a) : "l"(p));
    return a;
}
#define SMEM_SWIZZLE_128B(off) ((off) ^ (((off) >> 3) & 0x70))

__device__ __forceinline__ void ldsm_x4(uint32_t& r0, uint32_t& r1,
                                        uint32_t& r2, uint32_t& r3,
                                        uint32_t addr) {
    asm volatile("ldmatrix.sync.aligned.m8n8.x4.shared.b16 {%0,%1,%2,%3}, [%4];"
                 : "=r"(r0), "=r"(r1), "=r"(r2), "=r"(r3) : "r"(addr));
}
__device__ __forceinline__ void ldsm_x4_t(uint32_t& r0, uint32_t& r1,
                                          uint32_t& r2, uint32_t& r3,
                                          uint32_t addr) {
    asm volatile("ldmatrix.sync.aligned.m8n8.x4.trans.shared.b16 {%0,%1,%2,%3}, [%4];"
                 : "=r"(r0), "=r"(r1), "=r"(r2), "=r"(r3) : "r"(addr));
}
__device__ __forceinline__ void mma16816(float* c, const uint32_t* a,
                                         const uint32_t* b) {
    asm volatile(
        "mma.sync.aligned.m16n8k16.row.col.f32.f16.f16.f32 "
        "{%0,%1,%2,%3}, {%4,%5,%6,%7}, {%8,%9}, {%0,%1,%2,%3};"
        : "+f"(c[0]), "+f"(c[1]), "+f"(c[2]), "+f"(c[3])
        : "r"(a[0]), "r"(a[1]), "r"(a[2]), "r"(a[3]), "r"(b[0]), "r"(b[1]));
}
__device__ __forceinline__ uint32_t packhf(float lo, float hi) {
    __half2 t = __floats2half2_rn(lo, hi);   // .x -> low 16 bits
    return *reinterpret_cast<uint32_t*>(&t);
}
__device__ __forceinline__ float hres(float c) {
    return c - __half2float(__float2half_rn(c));
}
__device__ __forceinline__ void cp16(uint32_t s, const void* g) {
    asm volatile("cp.async.cg.shared.global [%0], [%1], 16;" :: "r"(s), "l"(g));
}
#define CP_COMMIT() asm volatile("cp.async.commit_group;")
#define CP_WAIT(n)  asm volatile("cp.async.wait_group %0;" :: "n"(n))

// ---------------- fused prep: x split + 4 weight transposes + rope table -----
__global__ void prep_kernel(const float* __restrict__ x,
                            const float* __restrict__ Wq,
                            const float* __restrict__ Wk,
                            const float* __restrict__ Wv,
                            const float* __restrict__ Wo,
                            const int* __restrict__ offset_ptr,
                            __half* __restrict__ xhi,
                            __half* __restrict__ xlo,
                            __half* __restrict__ wqkv,
                            __half* __restrict__ wo,
                            float2* __restrict__ ropeTab) {
    const int z = blockIdx.z;
    const int tx = threadIdx.x, ty = threadIdx.y;

    if (z == 4) {   // split x
        int i = (blockIdx.y * 128 + blockIdx.x) * 256 + ty * 32 + tx;
        float4 v = reinterpret_cast<const float4*>(x)[i];
        uint32_t* hp = reinterpret_cast<uint32_t*>(xhi) + 2 * i;
        uint32_t* lp = reinterpret_cast<uint32_t*>(xlo) + 2 * i;
        hp[0] = packhf(v.x, v.y); hp[1] = packhf(v.z, v.w);
        lp[0] = packhf(hres(v.x), hres(v.y));
        lp[1] = packhf(hres(v.z), hres(v.w));
        return;
    }
    if (z == 5) {   // rope table: 2048 x 32 entries
        int bid = blockIdx.y * 128 + blockIdx.x;
        if (bid >= 256) return;
        int i = bid * 256 + ty * 32 + tx;      // 0..65535
        int s = i >> 5, j = i & 31;
        float pos = (float)(s + offset_ptr[0]);
        float inv = powf(10000.0f, -(float)j / 32.0f);
        float ang = pos * inv;
        ropeTab[i] = make_float2(cosf(ang), sinf(ang));
        return;
    }

    const float* W;
    __half* hi;
    int N;
    if (z == 0)      { W = Wq; N = DMODEL; hi = wqkv; }
    else if (z == 1) { W = Wk; N = DKV; hi = wqkv + (size_t)DMODEL * KDIM; }
    else if (z == 2) { W = Wv; N = DKV; hi = wqkv + (size_t)(DMODEL + DKV) * KDIM; }
    else             { W = Wo; N = DMODEL; hi = wo; }

    int nb = blockIdx.x * 32;
    if (nb >= N) return;
    int kb = blockIdx.y * 32;

    __shared__ float tile[32][33];
    for (int i = ty; i < 32; i += 8)
        tile[i][tx] = W[(size_t)(kb + i) * N + nb + tx];
    __syncthreads();
    for (int i = ty; i < 32; i += 8) {
        float v = tile[tx][i];
        hi[(size_t)(nb + i) * KDIM + kb + tx] = __float2half_rn(v);
    }
}

// ---------------- shared GEMM mainloop (macro, R12 config) --------------------
// 512 threads, 16 warps in 4m x 4n grid, warp tile 32x32.
// fp16 2-term: C = Ahi*B + Alo*B. 2-stage cp.async, CHUNK=64 (128B rows, SW128).
#define CHUNK 64
#define NCH   (KDIM / CHUNK)          // 16
#define STG_BYTES 49152               // Ahi 16K | Alo 16K | B 16K
#define GEMM_SMEM_BYTES (2 * STG_BYTES + 1024)

#define GQ_LOAD_CHUNK(ch_, stg_) do {                                          \
        const int k0_ = (ch_) * CHUNK;                                         \
        uint32_t sb0_ = smem_u32(sm + (stg_) * STG_BYTES);                     \
        _Pragma("unroll")                                                      \
        for (int ii = 0; ii < 2; ii++) {                                       \
            int idx_ = t + ii * 512;                                           \
            int row_ = idx_ >> 3;                                              \
            int c_ = idx_ & 7;                                                 \
            uint32_t sw_ = SMEM_SWIZZLE_128B((uint32_t)(row_ * 128 + c_ * 16));\
            size_t ao_ = (size_t)(rowBase + row_) * KDIM + k0_ + c_ * 8;       \
            size_t bo_ = (size_t)(colBase + row_) * KDIM + k0_ + c_ * 8;       \
            cp16(sb0_ + sw_, Ahi + ao_);                                       \
            cp16(sb0_ + 16384 + sw_, Alo + ao_);                               \
            cp16(sb0_ + 32768 + sw_, Bw + bo_);                                \
        }                                                                      \
    } while (0)

#define GQ_LOAD_FRAGS(s_) do {                                                 \
        _Pragma("unroll")                                                      \
        for (int mb = 0; mb < 2; mb++) {                                       \
            int row = warp_m * 32 + mb * 16 + a_row;                           \
            uint32_t sw = SMEM_SWIZZLE_128B(                                   \
                (uint32_t)(row * 128 + a_colB + (s_) * 32));                   \
            ldsm_x4(fa_hi[mb][0], fa_hi[mb][1], fa_hi[mb][2], fa_hi[mb][3],    \
                    aHi + sw);                                                 \
            ldsm_x4(fa_lo[mb][0], fa_lo[mb][1], fa_lo[mb][2], fa_lo[mb][3],    \
                    aLo + sw);                                                 \
        }                                                                      \
        _Pragma("unroll")                                                      \
        for (int p = 0; p < 2; p++) {                                          \
            int row = warp_n * 32 + p * 16 + b_rowl;                           \
            uint32_t sw = SMEM_SWIZZLE_128B(                                   \
                (uint32_t)(row * 128 + b_colB + (s_) * 32));                   \
            ldsm_x4(fb[2 * p][0], fb[2 * p][1],                                \
                    fb[2 * p + 1][0], fb[2 * p + 1][1], bW + sw);              \
        }                                                                      \
    } while (0)

#define GQ_MMA() do {                                                          \
        _Pragma("unroll")                                                      \
        for (int nb = 0; nb < 4; nb++)                                         \
            _Pragma("unroll")                                                  \
            for (int mb = 0; mb < 2; mb++)                                     \
                mma16816(acc[mb][nb], fa_hi[mb], fb[nb]);                      \
        _Pragma("unroll")                                                      \
        for (int nb = 0; nb < 4; nb++)                                         \
            _Pragma("unroll")                                                  \
            for (int mb = 0; mb < 2; mb++)                                     \
                mma16816(acc[mb][nb], fa_lo[mb], fb[nb]);                      \
    } while (0)

#define GEMM_MAINLOOP(Ahi, Alo, Bw)                                            \
    uint32_t base = (smem_u32(dsm) + 1023u) & ~1023u;                          \
    char* sm = dsm + (base - smem_u32(dsm));                                   \
    float acc[2][4][4];                                                        \
    _Pragma("unroll")                                                          \
    for (int mb = 0; mb < 2; mb++)                                             \
        _Pragma("unroll")                                                      \
        for (int nb = 0; nb < 4; nb++)                                         \
            _Pragma("unroll")                                                  \
            for (int q = 0; q < 4; q++) acc[mb][nb][q] = 0.f;                  \
    const int a_row = lid & 15;                                                \
    const int a_colB = (lid >> 4) * 16;                                        \
    const int b_rowl = ((lid >> 4) << 3) + (lid & 7);                          \
    const int b_colB = ((lid >> 3) & 1) * 16;                                  \
    uint32_t fa_hi[2][4], fa_lo[2][4];                                         \
    uint32_t fb[4][2];                                                         \
    GQ_LOAD_CHUNK(0, 0);                                                       \
    CP_COMMIT();                                                               \
    for (int ch = 0; ch < NCH; ch++) {                                         \
        CP_WAIT(0);                                                            \
        __syncthreads();                                                       \
        uint32_t stg0 = smem_u32(sm + (ch & 1) * STG_BYTES);                   \
        uint32_t aHi = stg0;                                                   \
        uint32_t aLo = stg0 + 16384;                                           \
        uint32_t bW = stg0 + 32768;                                            \
        _Pragma("unroll")                                                      \
        for (int s = 0; s < 4; s++) {                                          \
            GQ_LOAD_FRAGS(s);                                                  \
            if (s == 0 && ch + 1 < NCH) {                                      \
                GQ_LOAD_CHUNK(ch + 1, (ch + 1) & 1);                           \
                CP_COMMIT();                                                   \
            }                                                                  \
            GQ_MMA();                                                          \
        }                                                                      \
    }

// ---------------- GEMM with plain fp32 epilogue (O projection) ---------------
__global__ __launch_bounds__(512, 1) void gemm_mma3(
    const __half* __restrict__ Ahi, const __half* __restrict__ Alo,
    const __half* __restrict__ Bw,
    float* __restrict__ C, int Ncols) {
    extern __shared__ char dsm[];
    const int t = threadIdx.x;
    const int wid = t >> 5;
    const int lid = t & 31;
    const int warp_m = wid & 3;
    const int warp_n = wid >> 2;
    const int rowBase = blockIdx.y * 128;
    const int colBase = blockIdx.x * 128;

    GEMM_MAINLOOP(Ahi, Alo, Bw)

    const int g = lid >> 2;
    const int q = lid & 3;
#pragma unroll
    for (int mb = 0; mb < 2; mb++) {
#pragma unroll
        for (int nb = 0; nb < 4; nb++) {
            int row = rowBase + warp_m * 32 + mb * 16 + g;
            int col = colBase + warp_n * 32 + nb * 8 + q * 2;
            *reinterpret_cast<float2*>(&C[(size_t)row * Ncols + col]) =
                make_float2(acc[mb][nb][0], acc[mb][nb][1]);
            *reinterpret_cast<float2*>(&C[(size_t)(row + 8) * Ncols + col]) =
                make_float2(acc[mb][nb][2], acc[mb][nb][3]);
        }
    }
}

// ---------------- QKV GEMM with fused RoPE + hi/lo split epilogue ------------
// Q: hi/lo written. K: fp16 only (no residual). V: fp16 only.
__global__ __launch_bounds__(512, 1) void gemm_qkv(
    const __half* __restrict__ Ahi, const __half* __restrict__ Alo,
    const __half* __restrict__ Bw,
    __half* __restrict__ qhi, __half* __restrict__ qlo,
    __half* __restrict__ khi,
    __half* __restrict__ vhi,
    const float2* __restrict__ ropeTab) {
    extern __shared__ char dsm[];
    const int t = threadIdx.x;
    const int wid = t >> 5;
    const int lid = t & 31;
    const int warp_m = wid & 3;
    const int warp_n = wid >> 2;
    const int rowBase = blockIdx.y * 128;
    const int colBase = blockIdx.x * 128;

    GEMM_MAINLOOP(Ahi, Alo, Bw)

    const int g2 = lid >> 2;
    const int qd2 = (lid & 3) * 2;

    if (colBase >= DMODEL + DKV) {
        // V: plain fp16, direct from registers
        const int cb = colBase - DMODEL - DKV;
#pragma unroll
        for (int mb = 0; mb < 2; mb++) {
            int r0 = rowBase + warp_m * 32 + mb * 16 + g2;
#pragma unroll
            for (int nb = 0; nb < 4; nb++) {
                int col = cb + warp_n * 32 + nb * 8 + qd2;
                size_t o0 = (size_t)r0 * DKV + col;
                size_t o1 = (size_t)(r0 + 8) * DKV + col;
                *reinterpret_cast<uint32_t*>(vhi + o0) =
                    packhf(acc[mb][nb][0], acc[mb][nb][1]);
                *reinterpret_cast<uint32_t*>(vhi + o1) =
                    packhf(acc[mb][nb][2], acc[mb][nb][3]);
            }
        }
        return;
    }

    // Q/K: bounce accumulators through smem for cross-warp RoPE
    float* stile = reinterpret_cast<float*>(sm);   // [128][128] f32, XOR swizzle
    __syncthreads();   // all warps done with final-chunk fragment reads
#pragma unroll
    for (int mb = 0; mb < 2; mb++) {
#pragma unroll
        for (int nb = 0; nb < 4; nb++) {
            int rl0 = warp_m * 32 + mb * 16 + g2;
            int cw = warp_n * 32 + nb * 8 + qd2;
            uint32_t w0 = rl0 * 128 + (cw ^ ((rl0 & 7) << 3));
            uint32_t w1 = (rl0 + 8) * 128 + (cw ^ (((rl0 + 8) & 7) << 3));
            *reinterpret_cast<float2*>(stile + w0) =
                make_float2(acc[mb][nb][0], acc[mb][nb][1]);
            *reinterpret_cast<float2*>(stile + w1) =
                make_float2(acc[mb][nb][2], acc[mb][nb][3]);
        }
    }
    __syncthreads();

    const bool isQ = colBase < DMODEL;
    const float sc = isQ ? 0.125f : 1.0f;   // 1/sqrt(64) folded into Q
    __half* Hhi = isQ ? qhi : khi;
    const int ncols = isQ ? DMODEL : DKV;
    const int cbase = isQ ? colBase : colBase - DMODEL;

    // 128 rows x 2 heads x 16 j-pairs = 4096 items, 512 threads -> 8 iters
#pragma unroll
    for (int it = 0; it < 8; it++) {
        int i = t + it * 512;
        int j2 = i & 15;
        int head = (i >> 4) & 1;
        int rl = i >> 5;                 // local row 0..127
        int j = 2 * j2;
        int c1 = head * 64 + j;
        uint32_t xr = (uint32_t)((rl & 7) << 3);
        float2 ab0 = *reinterpret_cast<float2*>(stile + rl * 128 + (c1 ^ xr));
        float2 ab1 = *reinterpret_cast<float2*>(stile + rl * 128 + ((c1 + 32) ^ xr));
        int grow = rowBase + rl;
        int srow = grow & (SEQ - 1);
        float2 cs0 = ropeTab[srow * 32 + j];
        float2 cs1 = ropeTab[srow * 32 + j + 1];
        float a0 = ab0.x, a1 = ab0.y, b0 = ab1.x, b1 = ab1.y;
        float q0 = (a0 * cs0.x - b0 * cs0.y) * sc;
        float q1 = (a1 * cs1.x - b1 * cs1.y) * sc;
        float u0 = (b0 * cs0.x + a0 * cs0.y) * sc;
        float u1 = (b1 * cs1.x + a1 * cs1.y) * sc;
        size_t o = (size_t)grow * ncols + cbase + c1;
        *reinterpret_cast<uint32_t*>(Hhi + o) = packhf(q0, q1);
        *reinterpret_cast<uint32_t*>(Hhi + o + 32) = packhf(u0, u1);
        if (isQ) {
            *reinterpret_cast<uint32_t*>(qlo + o) = packhf(hres(q0), hres(q1));
            *reinterpret_cast<uint32_t*>(qlo + o + 32) = packhf(hres(u0), hres(u1));
        }
    }
}

// ---------------- tensor-core flash attention (causal, GQA) ------------------
// S = 2-term (Q hi/lo x K fp16), PV = 2-term (P hi/lo x V fp16).
#define KV_STG 16384                  // Khi 8K | Vhi 8K
#define ATTN2_SMEM (32768 + 2 * KV_STG + 1024)

__global__ __launch_bounds__(256, 1) void attn_mma(
    const __half* __restrict__ Qhi, const __half* __restrict__ Qlo,
    const __half* __restrict__ Khi,
    const __half* __restrict__ Vhi,
    __half* __restrict__ Ohi, __half* __restrict__ Olo) {
    extern __shared__ char dsm[];
    uint32_t base = (smem_u32(dsm) + 1023u) & ~1023u;
    char* sm = dsm + (base - smem_u32(dsm));
    char* sQhi = sm;            // 16KB
    char* sQlo = sm + 16384;    // 16KB

    const int qt = (int)gridDim.x - 1 - (int)blockIdx.x;   // heavy CTAs first
    const int h  = blockIdx.y;
    const int b  = blockIdx.z;
    const int hkv = h >> 2;
    const int t  = threadIdx.x;
    const int wid = t >> 5;
    const int lid = t & 31;
    const int g = lid >> 2;
    const int qd = lid & 3;
    const int q0 = qt * 128;

    const size_t kvbase = ((size_t)b * SEQ) * DKV + (size_t)hkv * HDIM;
    const int ntiles = 2 * qt + 2;

#define LOADKV(kt_, stg_) do {                                                  \
        const int k0_ = (kt_) * 64;                                            \
        uint32_t sb0_ = smem_u32(sm + 32768 + (stg_) * KV_STG);                 \
        _Pragma("unroll")                                                       \
        for (int ii = 0; ii < 2; ii++) {                                        \
            int idx_ = t + ii * 256;                                            \
            int row_ = idx_ >> 3;                                               \
            int ch_ = idx_ & 7;                                                 \
            uint32_t sw_ = SMEM_SWIZZLE_128B((uint32_t)(row_ * 128 + ch_ * 16));\
            size_t gl_ = kvbase + (size_t)(k0_ + row_) * DKV + ch_ * 8;         \
            cp16(sb0_ + sw_, Khi + gl_);                                        \
            cp16(sb0_ + 8192 + sw_, Vhi + gl_);                                 \
        }                                                                       \
    } while (0)

    // group A: Q hi/lo tiles via cp.async
    {
        const __half* Qh = Qhi + ((size_t)(b * SEQ + q0)) * DMODEL + h * HDIM;
        const __half* Ql = Qlo + ((size_t)(b * SEQ + q0)) * DMODEL + h * HDIM;
#pragma unroll
        for (int ii = 0; ii < 4; ii++) {
            int idx = t + ii * 256;        // 0..1023
            int row = idx >> 3;
            int ch = idx & 7;
            uint32_t sw = SMEM_SWIZZLE_128B((uint32_t)(row * 128 + ch * 16));
            size_t gl = (size_t)row * DMODEL + ch * 8;
            cp16(smem_u32(sQhi) + sw, Qh + gl);
            cp16(smem_u32(sQlo) + sw, Ql + gl);
        }
        CP_COMMIT();
    }
    // group B: KV tile 0
    LOADKV(0, 0);
    CP_COMMIT();

    CP_WAIT(1);        // Q tiles complete
    __syncthreads();

    // ---- Q fragments in registers
    uint32_t qh[4][4], ql[4][4];
    {
        int arow = wid * 16 + (lid & 15);
        int acolB = (lid >> 4) * 16;
#pragma unroll
        for (int s = 0; s < 4; s++) {
            uint32_t sw = SMEM_SWIZZLE_128B((uint32_t)(arow * 128 + acolB + s * 32));
            ldsm_x4(qh[s][0], qh[s][1], qh[s][2], qh[s][3], smem_u32(sQhi) + sw);
            ldsm_x4(ql[s][0], ql[s][1], ql[s][2], ql[s][3], smem_u32(sQlo) + sw);
        }
    }

    float o[8][4];
#pragma unroll
    for (int nb = 0; nb < 8; nb++)
#pragma unroll
        for (int q = 0; q < 4; q++) o[nb][q] = 0.f;
    float m0 = -1e30f, m1 = -1e30f, l0 = 0.f, l1 = 0.f;

    for (int kt = 0; kt < ntiles; kt++) {
        const int k0 = kt * 64;
        if (kt + 1 < ntiles) {
            LOADKV(kt + 1, (kt + 1) & 1);
            CP_COMMIT();
            CP_WAIT(1);
        } else {
            CP_WAIT(0);
        }
        __syncthreads();

        uint32_t kvb = smem_u32(sm + 32768 + (kt & 1) * KV_STG);
        uint32_t sKhi_ = kvb;
        uint32_t sVhi_ = kvb + 8192;

        // ---- S = Q K^T (2-term: Q hi/lo x K fp16, term-major issue)
        float sacc[8][4];
#pragma unroll
        for (int nb = 0; nb < 8; nb++)
#pragma unroll
            for (int q = 0; q < 4; q++) sacc[nb][q] = 0.f;

        {
            int brow = ((lid >> 4) << 3) + (lid & 7);
            int bcolB = ((lid >> 3) & 1) * 16;
#pragma unroll
            for (int s = 0; s < 4; s++) {
                uint32_t kh[8][2];
#pragma unroll
                for (int p = 0; p < 4; p++) {
                    uint32_t sw = SMEM_SWIZZLE_128B(
                        (uint32_t)((p * 16 + brow) * 128 + bcolB + s * 32));
                    ldsm_x4(kh[2 * p][0], kh[2 * p][1], kh[2 * p + 1][0],
                            kh[2 * p + 1][1], sKhi_ + sw);
                }
#pragma unroll
                for (int nb = 0; nb < 8; nb++)
                    mma16816(sacc[nb], qh[s], kh[nb]);
#pragma unroll
                for (int nb = 0; nb < 8; nb++)
                    mma16816(sacc[nb], ql[s], kh[nb]);
            }
        }

        // ---- causal mask (only diagonal tiles)
        if (kt >= 2 * qt) {
            int rowa = q0 + wid * 16 + g;
#pragma unroll
            for (int nb = 0; nb < 8; nb++) {
                int col = k0 + nb * 8 + qd * 2;
                if (col > rowa)     sacc[nb][0] = -1e30f;
                if (col + 1 > rowa) sacc[nb][1] = -1e30f;
                if (col > rowa + 8)     sacc[nb][2] = -1e30f;
                if (col + 1 > rowa + 8) sacc[nb][3] = -1e30f;
            }
        }

        // ---- online softmax
        {
            float mx0 = -1e30f, mx1 = -1e30f;
#pragma unroll
            for (int nb = 0; nb < 8; nb++) {
                mx0 = fmaxf(mx0, fmaxf(sacc[nb][0], sacc[nb][1]));
                mx1 = fmaxf(mx1, fmaxf(sacc[nb][2], sacc[nb][3]));
            }
            mx0 = fmaxf(mx0, __shfl_xor_sync(0xffffffff, mx0, 1));
            mx0 = fmaxf(mx0, __shfl_xor_sync(0xffffffff, mx0, 2));
            mx1 = fmaxf(mx1, __shfl_xor_sync(0xffffffff, mx1, 1));
            mx1 = fmaxf(mx1, __shfl_xor_sync(0xffffffff, mx1, 2));
            float mn0 = fmaxf(m0, mx0), mn1 = fmaxf(m1, mx1);
            float al0 = __expf(m0 - mn0), al1 = __expf(m1 - mn1);
            m0 = mn0; m1 = mn1;
            l0 *= al0; l1 *= al1;
            float la0 = 0.f, la1 = 0.f;
#pragma unroll
            for (int nb = 0; nb < 8; nb++) {
                sacc[nb][0] = __expf(sacc[nb][0] - mn0);
                sacc[nb][1] = __expf(sacc[nb][1] - mn0);
                sacc[nb][2] = __expf(sacc[nb][2] - mn1);
                sacc[nb][3] = __expf(sacc[nb][3] - mn1);
                la0 += sacc[nb][0] + sacc[nb][1];
                la1 += sacc[nb][2] + sacc[nb][3];
                o[nb][0] *= al0; o[nb][1] *= al0;
                o[nb][2] *= al1; o[nb][3] *= al1;
            }
            l0 += la0; l1 += la1;
        }

        // ---- pack P hi/lo as A-fragments (fp16)
        uint32_t ph[4][4], pl[4][4];
#pragma unroll
        for (int j = 0; j < 4; j++) {
            float* c = sacc[2 * j];
            float* d = sacc[2 * j + 1];
            ph[j][0] = packhf(c[0], c[1]);
            ph[j][1] = packhf(c[2], c[3]);
            ph[j][2] = packhf(d[0], d[1]);
            ph[j][3] = packhf(d[2], d[3]);
            pl[j][0] = packhf(hres(c[0]), hres(c[1]));
            pl[j][1] = packhf(hres(c[2]), hres(c[3]));
            pl[j][2] = packhf(hres(d[0]), hres(d[1]));
            pl[j][3] = packhf(hres(d[2]), hres(d[3]));
        }

        // ---- O += P V (2-term: P hi/lo x V fp16), V via ldmatrix.trans
        {
            int vrow = (lid & 15);
            int vcolB = (lid >> 4) * 16;
#pragma unroll
            for (int j = 0; j < 4; j++) {
                uint32_t vh[8][2];
#pragma unroll
                for (int dj = 0; dj < 4; dj++) {
                    uint32_t sw = SMEM_SWIZZLE_128B(
                        (uint32_t)((j * 16 + vrow) * 128 + dj * 32 + vcolB));
                    ldsm_x4_t(vh[2 * dj][0], vh[2 * dj][1], vh[2 * dj + 1][0],
                              vh[2 * dj + 1][1], sVhi_ + sw);
                }
#pragma unroll
                for (int nb = 0; nb < 8; nb++)
                    mma16816(o[nb], ph[j], vh[nb]);
#pragma unroll
                for (int nb = 0; nb < 8; nb++)
                    mma16816(o[nb], pl[j], vh[nb]);
            }
        }
        __syncthreads();
    }
#undef LOADKV

    // ---- finalize: normalize, write fp16 hi/lo (fused split)
    l0 += __shfl_xor_sync(0xffffffff, l0, 1);
    l0 += __shfl_xor_sync(0xffffffff, l0, 2);
    l1 += __shfl_xor_sync(0xffffffff, l1, 1);
    l1 += __shfl_xor_sync(0xffffffff, l1, 2);
    float inv0 = 1.0f / l0, inv1 = 1.0f / l1;

    int rowa = q0 + wid * 16 + g;
    size_t oa = ((size_t)(b * SEQ + rowa)) * DMODEL + h * HDIM;
    size_t ob = ((size_t)(b * SEQ + rowa + 8)) * DMODEL + h * HDIM;
#pragma unroll
    for (int nb = 0; nb < 8; nb++) {
        int col = nb * 8 + qd * 2;
        float a0 = o[nb][0] * inv0, a1 = o[nb][1] * inv0;
        float b0 = o[nb][2] * inv1, b1 = o[nb][3] * inv1;
        *reinterpret_cast<uint32_t*>(Ohi + oa + col) = packhf(a0, a1);
        *reinterpret_cast<uint32_t*>(Olo + oa + col) = packhf(hres(a0), hres(a1));
        *reinterpret_cast<uint32_t*>(Ohi + ob + col) = packhf(b0, b1);
        *reinterpret_cast<uint32_t*>(Olo + ob + col) = packhf(hres(b0), hres(b1));
    }
}

// ---------------- launch ------------------------------------------------------
extern "C" void kernel_launch(void* const* d_in, const int* in_sizes, int n_in,
                              void* d_out, int out_size) {
    (void)in_sizes; (void)n_in; (void)out_size;
    const float* x  = (const float*)d_in[0];
    const float* Wq = (const float*)d_in[1];
    const float* Wk = (const float*)d_in[2];
    const float* Wv = (const float*)d_in[3];
    const float* Wo = (const float*)d_in[4];
    const int* poff = (const int*)d_in[5];
    float* out = (float*)d_out;

    __half *xhi, *xlo, *qhi, *qlo, *khi, *vhi, *wqkv, *wo;
    float2* rtab;
    cudaGetSymbolAddress((void**)&xhi, g_xhi);
    cudaGetSymbolAddress((void**)&xlo, g_xlo);
    cudaGetSymbolAddress((void**)&qhi, g_Qhi);
    cudaGetSymbolAddress((void**)&qlo, g_Qlo);
    cudaGetSymbolAddress((void**)&khi, g_Khi);
    cudaGetSymbolAddress((void**)&vhi, g_Vhi);
    cudaGetSymbolAddress((void**)&wqkv, g_wqkv);
    cudaGetSymbolAddress((void**)&wo, g_wo);
    cudaGetSymbolAddress((void**)&rtab, g_rope);

    cudaFuncSetAttribute(gemm_mma3, cudaFuncAttributeMaxDynamicSharedMemorySize,
                         GEMM_SMEM_BYTES);
    cudaFuncSetAttribute(gemm_qkv, cudaFuncAttributeMaxDynamicSharedMemorySize,
                         GEMM_SMEM_BYTES);
    cudaFuncSetAttribute(attn_mma, cudaFuncAttributeMaxDynamicSharedMemorySize,
                         ATTN2_SMEM);

    // fused prep: x split + weight transposes + rope table (one launch)
    prep_kernel<<<dim3(128, 32, 6), dim3(32, 8)>>>(
        x, Wq, Wk, Wv, Wo, poff, xhi, xlo, wqkv, wo, rtab);

    // fused QKV projection + RoPE + split epilogue (512 thr)
    gemm_qkv<<<dim3(NQKV / 128, ROWS / 128), 512, GEMM_SMEM_BYTES>>>(
        xhi, xlo, wqkv, qhi, qlo, khi, vhi, rtab);

    // attention -> writes hi/lo directly into xhi/xlo
    attn_mma<<<dim3(SEQ / 128, NHEADS, BATCH), 256, ATTN2_SMEM>>>(
        qhi, qlo, khi, vhi, xhi, xlo);

    // O projection (512 thr)
    gemm_mma3<<<dim3(DMODEL / 128, ROWS / 128), 512, GEMM_SMEM_BYTES>>>(
        xhi, xlo, wo, out, DMODEL);
}

// round 15
// speedup vs baseline: 1.4152x; 1.2787x over previous
#include <cuda_runtime.h>
#include <cuda_fp16.h>
#include <math.h>
#include <cstdint>

// Problem constants
#define BATCH 2
#define SEQ   2048
#define DMODEL 1024
#define NHEADS 16
#define NKV    4
#define HDIM   64
#define ROWS   (BATCH * SEQ)          // 4096
#define DKV    (NKV * HDIM)           // 256
#define KDIM   1024
#define NQKV   (DMODEL + 2 * DKV)     // 1536

// ---------------- scratch (static __device__, no allocation) ----------------
__device__ __half g_xhi[ROWS * DMODEL];     // x split; reused for attn out
__device__ __half g_xlo[ROWS * DMODEL];
__device__ __half g_Qhi[ROWS * DMODEL];     // Q plain fp16 (roped+scaled)
__device__ __half g_Khi[ROWS * DKV];        // K plain fp16 (roped)
__device__ __half g_Vhi[ROWS * DKV];
__device__ __half g_wqkv[NQKV * KDIM];      // transposed [N,K], fp16
__device__ __half g_wo[DMODEL * KDIM];
__device__ float2 g_rope[SEQ * 32];         // (cos, sin) per (s, j)

__device__ __forceinline__ uint32_t smem_u32(const void* p) {
    uint32_t a;
    asm("{ .reg .u64 t; cvta.to.shared.u64 t, %1; cvt.u32.u64 %0, t; }"
        : "=r"(a) : "l"(p));
    return a;
}
#define SMEM_SWIZZLE_128B(off) ((off) ^ (((off) >> 3) & 0x70))

__device__ __forceinline__ void ldsm_x4(uint32_t& r0, uint32_t& r1,
                                        uint32_t& r2, uint32_t& r3,
                                        uint32_t addr) {
    asm volatile("ldmatrix.sync.aligned.m8n8.x4.shared.b16 {%0,%1,%2,%3}, [%4];"
                 : "=r"(r0), "=r"(r1), "=r"(r2), "=r"(r3) : "r"(addr));
}
__device__ __forceinline__ void ldsm_x4_t(uint32_t& r0, uint32_t& r1,
                                          uint32_t& r2, uint32_t& r3,
                                          uint32_t addr) {
    asm volatile("ldmatrix.sync.aligned.m8n8.x4.trans.shared.b16 {%0,%1,%2,%3}, [%4];"
                 : "=r"(r0), "=r"(r1), "=r"(r2), "=r"(r3) : "r"(addr));
}
__device__ __forceinline__ void mma16816(float* c, const uint32_t* a,
                                         const uint32_t* b) {
    asm volatile(
        "mma.sync.aligned.m16n8k16.row.col.f32.f16.f16.f32 "
        "{%0,%1,%2,%3}, {%4,%5,%6,%7}, {%8,%9}, {%0,%1,%2,%3};"
        : "+f"(c[0]), "+f"(c[1]), "+f"(c[2]), "+f"(c[3])
        : "r"(a[0]), "r"(a[1]), "r"(a[2]), "r"(a[3]), "r"(b[0]), "r"(b[1]));
}
__device__ __forceinline__ uint32_t packhf(float lo, float hi) {
    __half2 t = __floats2half2_rn(lo, hi);   // .x -> low 16 bits
    return *reinterpret_cast<uint32_t*>(&t);
}
__device__ __forceinline__ float hres(float c) {
    return c - __half2float(__float2half_rn(c));
}
__device__ __forceinline__ void cp16(uint32_t s, const void* g) {
    asm volatile("cp.async.cg.shared.global [%0], [%1], 16;" :: "r"(s), "l"(g));
}
#define CP_COMMIT() asm volatile("cp.async.commit_group;")
#define CP_WAIT(n)  asm volatile("cp.async.wait_group %0;" :: "n"(n))

// ---------------- fused prep: x split + 4 weight transposes + rope table -----
__global__ void prep_kernel(const float* __restrict__ x,
                            const float* __restrict__ Wq,
                            const float* __restrict__ Wk,
                            const float* __restrict__ Wv,
                            const float* __restrict__ Wo,
                            const int* __restrict__ offset_ptr,
                            __half* __restrict__ xhi,
                            __half* __restrict__ xlo,
                            __half* __restrict__ wqkv,
                            __half* __restrict__ wo,
                            float2* __restrict__ ropeTab) {
    const int z = blockIdx.z;
    const int tx = threadIdx.x, ty = threadIdx.y;

    if (z == 4) {   // split x
        int i = (blockIdx.y * 128 + blockIdx.x) * 256 + ty * 32 + tx;
        float4 v = reinterpret_cast<const float4*>(x)[i];
        uint32_t* hp = reinterpret_cast<uint32_t*>(xhi) + 2 * i;
        uint32_t* lp = reinterpret_cast<uint32_t*>(xlo) + 2 * i;
        hp[0] = packhf(v.x, v.y); hp[1] = packhf(v.z, v.w);
        lp[0] = packhf(hres(v.x), hres(v.y));
        lp[1] = packhf(hres(v.z), hres(v.w));
        return;
    }
    if (z == 5) {   // rope table: 2048 x 32 entries
        int bid = blockIdx.y * 128 + blockIdx.x;
        if (bid >= 256) return;
        int i = bid * 256 + ty * 32 + tx;      // 0..65535
        int s = i >> 5, j = i & 31;
        float pos = (float)(s + offset_ptr[0]);
        float inv = powf(10000.0f, -(float)j / 32.0f);
        float ang = pos * inv;
        ropeTab[i] = make_float2(cosf(ang), sinf(ang));
        return;
    }

    const float* W;
    __half* hi;
    int N;
    if (z == 0)      { W = Wq; N = DMODEL; hi = wqkv; }
    else if (z == 1) { W = Wk; N = DKV; hi = wqkv + (size_t)DMODEL * KDIM; }
    else if (z == 2) { W = Wv; N = DKV; hi = wqkv + (size_t)(DMODEL + DKV) * KDIM; }
    else             { W = Wo; N = DMODEL; hi = wo; }

    int nb = blockIdx.x * 32;
    if (nb >= N) return;
    int kb = blockIdx.y * 32;

    __shared__ float tile[32][33];
    for (int i = ty; i < 32; i += 8)
        tile[i][tx] = W[(size_t)(kb + i) * N + nb + tx];
    __syncthreads();
    for (int i = ty; i < 32; i += 8) {
        float v = tile[tx][i];
        hi[(size_t)(nb + i) * KDIM + kb + tx] = __float2half_rn(v);
    }
}

// ---------------- shared GEMM mainloop (macro, R12 config) --------------------
// 512 threads, 16 warps in 4m x 4n grid, warp tile 32x32.
// TWOT=1: C = Ahi*B + Alo*B; TWOT=0: C = Ahi*B.
// 2-stage cp.async, CHUNK=64 (128B rows, SW128).
#define CHUNK 64
#define NCH   (KDIM / CHUNK)          // 16
#define STG_BYTES 49152               // Ahi 16K | Alo 16K | B 16K
#define GEMM_SMEM_BYTES (2 * STG_BYTES + 1024)

#define GQ_LOAD_CHUNK(ch_, stg_, TWOT) do {                                    \
        const int k0_ = (ch_) * CHUNK;                                         \
        uint32_t sb0_ = smem_u32(sm + (stg_) * STG_BYTES);                     \
        _Pragma("unroll")                                                      \
        for (int ii = 0; ii < 2; ii++) {                                       \
            int idx_ = t + ii * 512;                                           \
            int row_ = idx_ >> 3;                                              \
            int c_ = idx_ & 7;                                                 \
            uint32_t sw_ = SMEM_SWIZZLE_128B((uint32_t)(row_ * 128 + c_ * 16));\
            size_t ao_ = (size_t)(rowBase + row_) * KDIM + k0_ + c_ * 8;       \
            size_t bo_ = (size_t)(colBase + row_) * KDIM + k0_ + c_ * 8;       \
            cp16(sb0_ + sw_, Ahi + ao_);                                       \
            if (TWOT) cp16(sb0_ + 16384 + sw_, Alo + ao_);                     \
            cp16(sb0_ + 32768 + sw_, Bw + bo_);                                \
        }                                                                      \
    } while (0)

#define GQ_LOAD_FRAGS(s_, TWOT) do {                                           \
        _Pragma("unroll")                                                      \
        for (int mb = 0; mb < 2; mb++) {                                       \
            int row = warp_m * 32 + mb * 16 + a_row;                           \
            uint32_t sw = SMEM_SWIZZLE_128B(                                   \
                (uint32_t)(row * 128 + a_colB + (s_) * 32));                   \
            ldsm_x4(fa_hi[mb][0], fa_hi[mb][1], fa_hi[mb][2], fa_hi[mb][3],    \
                    aHi + sw);                                                 \
            if (TWOT)                                                          \
                ldsm_x4(fa_lo[mb][0], fa_lo[mb][1], fa_lo[mb][2],              \
                        fa_lo[mb][3], aLo + sw);                               \
        }                                                                      \
        _Pragma("unroll")                                                      \
        for (int p = 0; p < 2; p++) {                                          \
            int row = warp_n * 32 + p * 16 + b_rowl;                           \
            uint32_t sw = SMEM_SWIZZLE_128B(                                   \
                (uint32_t)(row * 128 + b_colB + (s_) * 32));                   \
            ldsm_x4(fb[2 * p][0], fb[2 * p][1],                                \
                    fb[2 * p + 1][0], fb[2 * p + 1][1], bW + sw);              \
        }                                                                      \
    } while (0)

#define GQ_MMA(TWOT) do {                                                      \
        _Pragma("unroll")                                                      \
        for (int nb = 0; nb < 4; nb++)                                         \
            _Pragma("unroll")                                                  \
            for (int mb = 0; mb < 2; mb++)                                     \
                mma16816(acc[mb][nb], fa_hi[mb], fb[nb]);                      \
        if (TWOT) {                                                            \
            _Pragma("unroll")                                                  \
            for (int nb = 0; nb < 4; nb++)                                     \
                _Pragma("unroll")                                              \
                for (int mb = 0; mb < 2; mb++)                                 \
                    mma16816(acc[mb][nb], fa_lo[mb], fb[nb]);                  \
        }                                                                      \
    } while (0)

#define GEMM_MAINLOOP(Ahi, Alo, Bw, TWOT)                                      \
    uint32_t base = (smem_u32(dsm) + 1023u) & ~1023u;                          \
    char* sm = dsm + (base - smem_u32(dsm));                                   \
    float acc[2][4][4];                                                        \
    _Pragma("unroll")                                                          \
    for (int mb = 0; mb < 2; mb++)                                             \
        _Pragma("unroll")                                                      \
        for (int nb = 0; nb < 4; nb++)                                         \
            _Pragma("unroll")                                                  \
            for (int q = 0; q < 4; q++) acc[mb][nb][q] = 0.f;                  \
    const int a_row = lid & 15;                                                \
    const int a_colB = (lid >> 4) * 16;                                        \
    const int b_rowl = ((lid >> 4) << 3) + (lid & 7);                          \
    const int b_colB = ((lid >> 3) & 1) * 16;                                  \
    uint32_t fa_hi[2][4], fa_lo[2][4];                                         \
    uint32_t fb[4][2];                                                         \
    (void)fa_lo;                                                               \
    GQ_LOAD_CHUNK(0, 0, TWOT);                                                 \
    CP_COMMIT();                                                               \
    for (int ch = 0; ch < NCH; ch++) {                                         \
        CP_WAIT(0);                                                            \
        __syncthreads();                                                       \
        uint32_t stg0 = smem_u32(sm + (ch & 1) * STG_BYTES);                   \
        uint32_t aHi = stg0;                                                   \
        uint32_t aLo = stg0 + 16384;                                           \
        uint32_t bW = stg0 + 32768;                                            \
        (void)aLo;                                                             \
        _Pragma("unroll")                                                      \
        for (int s = 0; s < 4; s++) {                                          \
            GQ_LOAD_FRAGS(s, TWOT);                                            \
            if (s == 0 && ch + 1 < NCH) {                                      \
                GQ_LOAD_CHUNK(ch + 1, (ch + 1) & 1, TWOT);                     \
                CP_COMMIT();                                                   \
            }                                                                  \
            GQ_MMA(TWOT);                                                      \
        }                                                                      \
    }

// ---------------- 1-term GEMM, fp32 epilogue (O projection) ------------------
__global__ __launch_bounds__(512, 1) void gemm_o(
    const __half* __restrict__ Ahi, const __half* __restrict__ Alo,
    const __half* __restrict__ Bw,
    float* __restrict__ C, int Ncols) {
    extern __shared__ char dsm[];
    const int t = threadIdx.x;
    const int wid = t >> 5;
    const int lid = t & 31;
    const int warp_m = wid & 3;
    const int warp_n = wid >> 2;
    const int rowBase = blockIdx.y * 128;
    const int colBase = blockIdx.x * 128;

    GEMM_MAINLOOP(Ahi, Alo, Bw, 0)

    const int g = lid >> 2;
    const int q = lid & 3;
#pragma unroll
    for (int mb = 0; mb < 2; mb++) {
#pragma unroll
        for (int nb = 0; nb < 4; nb++) {
            int row = rowBase + warp_m * 32 + mb * 16 + g;
            int col = colBase + warp_n * 32 + nb * 8 + q * 2;
            *reinterpret_cast<float2*>(&C[(size_t)row * Ncols + col]) =
                make_float2(acc[mb][nb][0], acc[mb][nb][1]);
            *reinterpret_cast<float2*>(&C[(size_t)(row + 8) * Ncols + col]) =
                make_float2(acc[mb][nb][2], acc[mb][nb][3]);
        }
    }
}

// ---------------- QKV GEMM (2-term) with fused RoPE + fp16 epilogue ----------
__global__ __launch_bounds__(512, 1) void gemm_qkv(
    const __half* __restrict__ Ahi, const __half* __restrict__ Alo,
    const __half* __restrict__ Bw,
    __half* __restrict__ qhi,
    __half* __restrict__ khi,
    __half* __restrict__ vhi,
    const float2* __restrict__ ropeTab) {
    extern __shared__ char dsm[];
    const int t = threadIdx.x;
    const int wid = t >> 5;
    const int lid = t & 31;
    const int warp_m = wid & 3;
    const int warp_n = wid >> 2;
    const int rowBase = blockIdx.y * 128;
    const int colBase = blockIdx.x * 128;

    GEMM_MAINLOOP(Ahi, Alo, Bw, 1)

    const int g2 = lid >> 2;
    const int qd2 = (lid & 3) * 2;

    if (colBase >= DMODEL + DKV) {
        // V: plain fp16, direct from registers
        const int cb = colBase - DMODEL - DKV;
#pragma unroll
        for (int mb = 0; mb < 2; mb++) {
            int r0 = rowBase + warp_m * 32 + mb * 16 + g2;
#pragma unroll
            for (int nb = 0; nb < 4; nb++) {
                int col = cb + warp_n * 32 + nb * 8 + qd2;
                size_t o0 = (size_t)r0 * DKV + col;
                size_t o1 = (size_t)(r0 + 8) * DKV + col;
                *reinterpret_cast<uint32_t*>(vhi + o0) =
                    packhf(acc[mb][nb][0], acc[mb][nb][1]);
                *reinterpret_cast<uint32_t*>(vhi + o1) =
                    packhf(acc[mb][nb][2], acc[mb][nb][3]);
            }
        }
        return;
    }

    // Q/K: bounce accumulators through smem for cross-warp RoPE
    float* stile = reinterpret_cast<float*>(sm);   // [128][128] f32, XOR swizzle
    __syncthreads();   // all warps done with final-chunk fragment reads
#pragma unroll
    for (int mb = 0; mb < 2; mb++) {
#pragma unroll
        for (int nb = 0; nb < 4; nb++) {
            int rl0 = warp_m * 32 + mb * 16 + g2;
            int cw = warp_n * 32 + nb * 8 + qd2;
            uint32_t w0 = rl0 * 128 + (cw ^ ((rl0 & 7) << 3));
            uint32_t w1 = (rl0 + 8) * 128 + (cw ^ (((rl0 + 8) & 7) << 3));
            *reinterpret_cast<float2*>(stile + w0) =
                make_float2(acc[mb][nb][0], acc[mb][nb][1]);
            *reinterpret_cast<float2*>(stile + w1) =
                make_float2(acc[mb][nb][2], acc[mb][nb][3]);
        }
    }
    __syncthreads();

    const bool isQ = colBase < DMODEL;
    const float sc = isQ ? 0.125f : 1.0f;   // 1/sqrt(64) folded into Q
    __half* Hhi = isQ ? qhi : khi;
    const int ncols = isQ ? DMODEL : DKV;
    const int cbase = isQ ? colBase : colBase - DMODEL;

    // 128 rows x 2 heads x 16 j-pairs = 4096 items, 512 threads -> 8 iters
#pragma unroll
    for (int it = 0; it < 8; it++) {
        int i = t + it * 512;
        int j2 = i & 15;
        int head = (i >> 4) & 1;
        int rl = i >> 5;                 // local row 0..127
        int j = 2 * j2;
        int c1 = head * 64 + j;
        uint32_t xr = (uint32_t)((rl & 7) << 3);
        float2 ab0 = *reinterpret_cast<float2*>(stile + rl * 128 + (c1 ^ xr));
        float2 ab1 = *reinterpret_cast<float2*>(stile + rl * 128 + ((c1 + 32) ^ xr));
        int grow = rowBase + rl;
        int srow = grow & (SEQ - 1);
        float2 cs0 = ropeTab[srow * 32 + j];
        float2 cs1 = ropeTab[srow * 32 + j + 1];
        float a0 = ab0.x, a1 = ab0.y, b0 = ab1.x, b1 = ab1.y;
        float q0 = (a0 * cs0.x - b0 * cs0.y) * sc;
        float q1 = (a1 * cs1.x - b1 * cs1.y) * sc;
        float u0 = (b0 * cs0.x + a0 * cs0.y) * sc;
        float u1 = (b1 * cs1.x + a1 * cs1.y) * sc;
        size_t o = (size_t)grow * ncols + cbase + c1;
        *reinterpret_cast<uint32_t*>(Hhi + o) = packhf(q0, q1);
        *reinterpret_cast<uint32_t*>(Hhi + o + 32) = packhf(u0, u1);
    }
}

// ---------------- tensor-core flash attention (causal, GQA) ------------------
// S = 1-term (Q fp16 x K fp16), PV = 1-term (P fp16 x V fp16).
#define KV_STG 16384                  // Khi 8K | Vhi 8K
#define ATTN2_SMEM (16384 + 2 * KV_STG + 1024)

__global__ __launch_bounds__(256, 2) void attn_mma(
    const __half* __restrict__ Qhi,
    const __half* __restrict__ Khi,
    const __half* __restrict__ Vhi,
    __half* __restrict__ Ohi) {
    extern __shared__ char dsm[];
    uint32_t base = (smem_u32(dsm) + 1023u) & ~1023u;
    char* sm = dsm + (base - smem_u32(dsm));
    char* sQhi = sm;            // 16KB

    const int qt = (int)gridDim.x - 1 - (int)blockIdx.x;   // heavy CTAs first
    const int h  = blockIdx.y;
    const int b  = blockIdx.z;
    const int hkv = h >> 2;
    const int t  = threadIdx.x;
    const int wid = t >> 5;
    const int lid = t & 31;
    const int g = lid >> 2;
    const int qd = lid & 3;
    const int q0 = qt * 128;

    const size_t kvbase = ((size_t)b * SEQ) * DKV + (size_t)hkv * HDIM;
    const int ntiles = 2 * qt + 2;

#define LOADKV(kt_, stg_) do {                                                  \
        const int k0_ = (kt_) * 64;                                            \
        uint32_t sb0_ = smem_u32(sm + 16384 + (stg_) * KV_STG);                 \
        _Pragma("unroll")                                                       \
        for (int ii = 0; ii < 2; ii++) {                                        \
            int idx_ = t + ii * 256;                                            \
            int row_ = idx_ >> 3;                                               \
            int ch_ = idx_ & 7;                                                 \
            uint32_t sw_ = SMEM_SWIZZLE_128B((uint32_t)(row_ * 128 + ch_ * 16));\
            size_t gl_ = kvbase + (size_t)(k0_ + row_) * DKV + ch_ * 8;         \
            cp16(sb0_ + sw_, Khi + gl_);                                        \
            cp16(sb0_ + 8192 + sw_, Vhi + gl_);                                 \
        }                                                                       \
    } while (0)

    // group A: Q tile via cp.async
    {
        const __half* Qh = Qhi + ((size_t)(b * SEQ + q0)) * DMODEL + h * HDIM;
#pragma unroll
        for (int ii = 0; ii < 4; ii++) {
            int idx = t + ii * 256;        // 0..1023
            int row = idx >> 3;
            int ch = idx & 7;
            uint32_t sw = SMEM_SWIZZLE_128B((uint32_t)(row * 128 + ch * 16));
            size_t gl = (size_t)row * DMODEL + ch * 8;
            cp16(smem_u32(sQhi) + sw, Qh + gl);
        }
        CP_COMMIT();
    }
    // group B: KV tile 0
    LOADKV(0, 0);
    CP_COMMIT();

    CP_WAIT(1);        // Q tile complete
    __syncthreads();

    // ---- Q fragments in registers
    uint32_t qh[4][4];
    {
        int arow = wid * 16 + (lid & 15);
        int acolB = (lid >> 4) * 16;
#pragma unroll
        for (int s = 0; s < 4; s++) {
            uint32_t sw = SMEM_SWIZZLE_128B((uint32_t)(arow * 128 + acolB + s * 32));
            ldsm_x4(qh[s][0], qh[s][1], qh[s][2], qh[s][3], smem_u32(sQhi) + sw);
        }
    }

    float o[8][4];
#pragma unroll
    for (int nb = 0; nb < 8; nb++)
#pragma unroll
        for (int q = 0; q < 4; q++) o[nb][q] = 0.f;
    float m0 = -1e30f, m1 = -1e30f, l0 = 0.f, l1 = 0.f;

    for (int kt = 0; kt < ntiles; kt++) {
        const int k0 = kt * 64;
        if (kt + 1 < ntiles) {
            LOADKV(kt + 1, (kt + 1) & 1);
            CP_COMMIT();
            CP_WAIT(1);
        } else {
            CP_WAIT(0);
        }
        __syncthreads();

        uint32_t kvb = smem_u32(sm + 16384 + (kt & 1) * KV_STG);
        uint32_t sKhi_ = kvb;
        uint32_t sVhi_ = kvb + 8192;

        // ---- S = Q K^T (1-term fp16)
        float sacc[8][4];
#pragma unroll
        for (int nb = 0; nb < 8; nb++)
#pragma unroll
            for (int q = 0; q < 4; q++) sacc[nb][q] = 0.f;

        {
            int brow = ((lid >> 4) << 3) + (lid & 7);
            int bcolB = ((lid >> 3) & 1) * 16;
#pragma unroll
            for (int s = 0; s < 4; s++) {
                uint32_t kh[8][2];
#pragma unroll
                for (int p = 0; p < 4; p++) {
                    uint32_t sw = SMEM_SWIZZLE_128B(
                        (uint32_t)((p * 16 + brow) * 128 + bcolB + s * 32));
                    ldsm_x4(kh[2 * p][0], kh[2 * p][1], kh[2 * p + 1][0],
                            kh[2 * p + 1][1], sKhi_ + sw);
                }
#pragma unroll
                for (int nb = 0; nb < 8; nb++)
                    mma16816(sacc[nb], qh[s], kh[nb]);
            }
        }

        // ---- causal mask (only diagonal tiles)
        if (kt >= 2 * qt) {
            int rowa = q0 + wid * 16 + g;
#pragma unroll
            for (int nb = 0; nb < 8; nb++) {
                int col = k0 + nb * 8 + qd * 2;
                if (col > rowa)     sacc[nb][0] = -1e30f;
                if (col + 1 > rowa) sacc[nb][1] = -1e30f;
                if (col > rowa + 8)     sacc[nb][2] = -1e30f;
                if (col + 1 > rowa + 8) sacc[nb][3] = -1e30f;
            }
        }

        // ---- online softmax
        {
            float mx0 = -1e30f, mx1 = -1e30f;
#pragma unroll
            for (int nb = 0; nb < 8; nb++) {
                mx0 = fmaxf(mx0, fmaxf(sacc[nb][0], sacc[nb][1]));
                mx1 = fmaxf(mx1, fmaxf(sacc[nb][2], sacc[nb][3]));
            }
            mx0 = fmaxf(mx0, __shfl_xor_sync(0xffffffff, mx0, 1));
            mx0 = fmaxf(mx0, __shfl_xor_sync(0xffffffff, mx0, 2));
            mx1 = fmaxf(mx1, __shfl_xor_sync(0xffffffff, mx1, 1));
            mx1 = fmaxf(mx1, __shfl_xor_sync(0xffffffff, mx1, 2));
            float mn0 = fmaxf(m0, mx0), mn1 = fmaxf(m1, mx1);
            float al0 = __expf(m0 - mn0), al1 = __expf(m1 - mn1);
            m0 = mn0; m1 = mn1;
            l0 *= al0; l1 *= al1;
            float la0 = 0.f, la1 = 0.f;
#pragma unroll
            for (int nb = 0; nb < 8; nb++) {
                sacc[nb][0] = __expf(sacc[nb][0] - mn0);
                sacc[nb][1] = __expf(sacc[nb][1] - mn0);
                sacc[nb][2] = __expf(sacc[nb][2] - mn1);
                sacc[nb][3] = __expf(sacc[nb][3] - mn1);
                la0 += sacc[nb][0] + sacc[nb][1];
                la1 += sacc[nb][2] + sacc[nb][3];
                o[nb][0] *= al0; o[nb][1] *= al0;
                o[nb][2] *= al1; o[nb][3] *= al1;
            }
            l0 += la0; l1 += la1;
        }

        // ---- pack P as fp16 A-fragments
        uint32_t ph[4][4];
#pragma unroll
        for (int j = 0; j < 4; j++) {
            float* c = sacc[2 * j];
            float* d = sacc[2 * j + 1];
            ph[j][0] = packhf(c[0], c[1]);
            ph[j][1] = packhf(c[2], c[3]);
            ph[j][2] = packhf(d[0], d[1]);
            ph[j][3] = packhf(d[2], d[3]);
        }

        // ---- O += P V (1-term), V via ldmatrix.trans
        {
            int vrow = (lid & 15);
            int vcolB = (lid >> 4) * 16;
#pragma unroll
            for (int j = 0; j < 4; j++) {
                uint32_t vh[8][2];
#pragma unroll
                for (int dj = 0; dj < 4; dj++) {
                    uint32_t sw = SMEM_SWIZZLE_128B(
                        (uint32_t)((j * 16 + vrow) * 128 + dj * 32 + vcolB));
                    ldsm_x4_t(vh[2 * dj][0], vh[2 * dj][1], vh[2 * dj + 1][0],
                              vh[2 * dj + 1][1], sVhi_ + sw);
                }
#pragma unroll
                for (int nb = 0; nb < 8; nb++)
                    mma16816(o[nb], ph[j], vh[nb]);
            }
        }
        __syncthreads();
    }
#undef LOADKV

    // ---- finalize: normalize, write fp16
    l0 += __shfl_xor_sync(0xffffffff, l0, 1);
    l0 += __shfl_xor_sync(0xffffffff, l0, 2);
    l1 += __shfl_xor_sync(0xffffffff, l1, 1);
    l1 += __shfl_xor_sync(0xffffffff, l1, 2);
    float inv0 = 1.0f / l0, inv1 = 1.0f / l1;

    int rowa = q0 + wid * 16 + g;
    size_t oa = ((size_t)(b * SEQ + rowa)) * DMODEL + h * HDIM;
    size_t ob = ((size_t)(b * SEQ + rowa + 8)) * DMODEL + h * HDIM;
#pragma unroll
    for (int nb = 0; nb < 8; nb++) {
        int col = nb * 8 + qd * 2;
        *reinterpret_cast<uint32_t*>(Ohi + oa + col) =
            packhf(o[nb][0] * inv0, o[nb][1] * inv0);
        *reinterpret_cast<uint32_t*>(Ohi + ob + col) =
            packhf(o[nb][2] * inv1, o[nb][3] * inv1);
    }
}

// ---------------- launch ------------------------------------------------------
extern "C" void kernel_launch(void* const* d_in, const int* in_sizes, int n_in,
                              void* d_out, int out_size) {
    (void)in_sizes; (void)n_in; (void)out_size;
    const float* x  = (const float*)d_in[0];
    const float* Wq = (const float*)d_in[1];
    const float* Wk = (const float*)d_in[2];
    const float* Wv = (const float*)d_in[3];
    const float* Wo = (const float*)d_in[4];
    const int* poff = (const int*)d_in[5];
    float* out = (float*)d_out;

    __half *xhi, *xlo, *qhi, *khi, *vhi, *wqkv, *wo;
    float2* rtab;
    cudaGetSymbolAddress((void**)&xhi, g_xhi);
    cudaGetSymbolAddress((void**)&xlo, g_xlo);
    cudaGetSymbolAddress((void**)&qhi, g_Qhi);
    cudaGetSymbolAddress((void**)&khi, g_Khi);
    cudaGetSymbolAddress((void**)&vhi, g_Vhi);
    cudaGetSymbolAddress((void**)&wqkv, g_wqkv);
    cudaGetSymbolAddress((void**)&wo, g_wo);
    cudaGetSymbolAddress((void**)&rtab, g_rope);

    cudaFuncSetAttribute(gemm_o, cudaFuncAttributeMaxDynamicSharedMemorySize,
                         GEMM_SMEM_BYTES);
    cudaFuncSetAttribute(gemm_qkv, cudaFuncAttributeMaxDynamicSharedMemorySize,
                         GEMM_SMEM_BYTES);
    cudaFuncSetAttribute(attn_mma, cudaFuncAttributeMaxDynamicSharedMemorySize,
                         ATTN2_SMEM);

    // fused prep: x split + weight transposes + rope table (one launch)
    prep_kernel<<<dim3(128, 32, 6), dim3(32, 8)>>>(
        x, Wq, Wk, Wv, Wo, poff, xhi, xlo, wqkv, wo, rtab);

    // fused QKV projection (2-term) + RoPE + fp16 epilogue (512 thr)
    gemm_qkv<<<dim3(NQKV / 128, ROWS / 128), 512, GEMM_SMEM_BYTES>>>(
        xhi, xlo, wqkv, qhi, khi, vhi, rtab);

    // attention (1-term S & PV) -> writes fp16 into xhi
    attn_mma<<<dim3(SEQ / 128, NHEADS, BATCH), 256, ATTN2_SMEM>>>(
        qhi, khi, vhi, xhi);

    // O projection (1-term, 512 thr)
    gemm_o<<<dim3(DMODEL / 128, ROWS / 128), 512, GEMM_SMEM_BYTES>>>(
        xhi, xhi /*unused*/, wo, out, DMODEL);
}

// round 16
// speedup vs baseline: 1.6427x; 1.1608x over previous
#include <cuda_runtime.h>
#include <cuda_fp16.h>
#include <math.h>
#include <cstdint>

// Problem constants
#define BATCH 2
#define SEQ   2048
#define DMODEL 1024
#define NHEADS 16
#define NKV    4
#define HDIM   64
#define ROWS   (BATCH * SEQ)          // 4096
#define DKV    (NKV * HDIM)           // 256
#define KDIM   1024
#define NQKV   (DMODEL + 2 * DKV)     // 1536

// ---------------- scratch (static __device__, no allocation) ----------------
__device__ __half g_xhi[ROWS * DMODEL];     // x fp16; reused for attn out
__device__ __half g_Qhi[ROWS * DMODEL];     // Q plain fp16 (roped+scaled)
__device__ __half g_Khi[ROWS * DKV];        // K plain fp16 (roped)
__device__ __half g_Vhi[ROWS * DKV];
__device__ __half g_wqkv[NQKV * KDIM];      // transposed [N,K], fp16
__device__ __half g_wo[DMODEL * KDIM];
__device__ float2 g_rope[SEQ * 32];         // (cos, sin) per (s, j)

__device__ __forceinline__ uint32_t smem_u32(const void* p) {
    uint32_t a;
    asm("{ .reg .u64 t; cvta.to.shared.u64 t, %1; cvt.u32.u64 %0, t; }"
        : "=r"(a) : "l"(p));
    return a;
}
#define SMEM_SWIZZLE_128B(off) ((off) ^ (((off) >> 3) & 0x70))

__device__ __forceinline__ void ldsm_x4(uint32_t& r0, uint32_t& r1,
                                        uint32_t& r2, uint32_t& r3,
                                        uint32_t addr) {
    asm volatile("ldmatrix.sync.aligned.m8n8.x4.shared.b16 {%0,%1,%2,%3}, [%4];"
                 : "=r"(r0), "=r"(r1), "=r"(r2), "=r"(r3) : "r"(addr));
}
__device__ __forceinline__ void ldsm_x4_t(uint32_t& r0, uint32_t& r1,
                                          uint32_t& r2, uint32_t& r3,
                                          uint32_t addr) {
    asm volatile("ldmatrix.sync.aligned.m8n8.x4.trans.shared.b16 {%0,%1,%2,%3}, [%4];"
                 : "=r"(r0), "=r"(r1), "=r"(r2), "=r"(r3) : "r"(addr));
}
__device__ __forceinline__ void mma16816(float* c, const uint32_t* a,
                                         const uint32_t* b) {
    asm volatile(
        "mma.sync.aligned.m16n8k16.row.col.f32.f16.f16.f32 "
        "{%0,%1,%2,%3}, {%4,%5,%6,%7}, {%8,%9}, {%0,%1,%2,%3};"
        : "+f"(c[0]), "+f"(c[1]), "+f"(c[2]), "+f"(c[3])
        : "r"(a[0]), "r"(a[1]), "r"(a[2]), "r"(a[3]), "r"(b[0]), "r"(b[1]));
}
__device__ __forceinline__ uint32_t packhf(float lo, float hi) {
    __half2 t = __floats2half2_rn(lo, hi);   // .x -> low 16 bits
    return *reinterpret_cast<uint32_t*>(&t);
}
__device__ __forceinline__ void cp16(uint32_t s, const void* g) {
    asm volatile("cp.async.cg.shared.global [%0], [%1], 16;" :: "r"(s), "l"(g));
}
#define CP_COMMIT() asm volatile("cp.async.commit_group;")
#define CP_WAIT(n)  asm volatile("cp.async.wait_group %0;" :: "n"(n))

// ---------------- fused prep: x convert + 4 weight transposes + rope table ---
__global__ void prep_kernel(const float* __restrict__ x,
                            const float* __restrict__ Wq,
                            const float* __restrict__ Wk,
                            const float* __restrict__ Wv,
                            const float* __restrict__ Wo,
                            const int* __restrict__ offset_ptr,
                            __half* __restrict__ xhi,
                            __half* __restrict__ wqkv,
                            __half* __restrict__ wo,
                            float2* __restrict__ ropeTab) {
    const int z = blockIdx.z;
    const int tx = threadIdx.x, ty = threadIdx.y;

    if (z == 4) {   // convert x to fp16
        int i = (blockIdx.y * 128 + blockIdx.x) * 256 + ty * 32 + tx;
        float4 v = reinterpret_cast<const float4*>(x)[i];
        uint32_t* hp = reinterpret_cast<uint32_t*>(xhi) + 2 * i;
        hp[0] = packhf(v.x, v.y); hp[1] = packhf(v.z, v.w);
        return;
    }
    if (z == 5) {   // rope table: 2048 x 32 entries
        int bid = blockIdx.y * 128 + blockIdx.x;
        if (bid >= 256) return;
        int i = bid * 256 + ty * 32 + tx;      // 0..65535
        int s = i >> 5, j = i & 31;
        float pos = (float)(s + offset_ptr[0]);
        float inv = powf(10000.0f, -(float)j / 32.0f);
        float ang = pos * inv;
        ropeTab[i] = make_float2(cosf(ang), sinf(ang));
        return;
    }

    const float* W;
    __half* hi;
    int N;
    if (z == 0)      { W = Wq; N = DMODEL; hi = wqkv; }
    else if (z == 1) { W = Wk; N = DKV; hi = wqkv + (size_t)DMODEL * KDIM; }
    else if (z == 2) { W = Wv; N = DKV; hi = wqkv + (size_t)(DMODEL + DKV) * KDIM; }
    else             { W = Wo; N = DMODEL; hi = wo; }

    int nb = blockIdx.x * 32;
    if (nb >= N) return;
    int kb = blockIdx.y * 32;

    __shared__ float tile[32][33];
    for (int i = ty; i < 32; i += 8)
        tile[i][tx] = W[(size_t)(kb + i) * N + nb + tx];
    __syncthreads();
    for (int i = ty; i < 32; i += 8) {
        float v = tile[tx][i];
        hi[(size_t)(nb + i) * KDIM + kb + tx] = __float2half_rn(v);
    }
}

// ---------------- shared GEMM mainloop (1-term fp16) --------------------------
// 512 threads, 16 warps in 4m x 4n grid, warp tile 32x32.
// C = A*B. 2-stage cp.async, CHUNK=64 (128B rows, SW128).
#define CHUNK 64
#define NCH   (KDIM / CHUNK)          // 16
#define STG_BYTES 32768               // A 16K | B 16K
#define GEMM_SMEM_BYTES (2 * STG_BYTES + 1024)

#define GQ_LOAD_CHUNK(ch_, stg_) do {                                          \
        const int k0_ = (ch_) * CHUNK;                                         \
        uint32_t sb0_ = smem_u32(sm + (stg_) * STG_BYTES);                     \
        _Pragma("unroll")                                                      \
        for (int ii = 0; ii < 2; ii++) {                                       \
            int idx_ = t + ii * 512;                                           \
            int row_ = idx_ >> 3;                                              \
            int c_ = idx_ & 7;                                                 \
            uint32_t sw_ = SMEM_SWIZZLE_128B((uint32_t)(row_ * 128 + c_ * 16));\
            size_t ao_ = (size_t)(rowBase + row_) * KDIM + k0_ + c_ * 8;       \
            size_t bo_ = (size_t)(colBase + row_) * KDIM + k0_ + c_ * 8;       \
            cp16(sb0_ + sw_, Aw + ao_);                                        \
            cp16(sb0_ + 16384 + sw_, Bw + bo_);                                \
        }                                                                      \
    } while (0)

#define GQ_LOAD_FRAGS(s_) do {                                                 \
        _Pragma("unroll")                                                      \
        for (int mb = 0; mb < 2; mb++) {                                       \
            int row = warp_m * 32 + mb * 16 + a_row;                           \
            uint32_t sw = SMEM_SWIZZLE_128B(                                   \
                (uint32_t)(row * 128 + a_colB + (s_) * 32));                   \
            ldsm_x4(fa[mb][0], fa[mb][1], fa[mb][2], fa[mb][3], aW + sw);      \
        }                                                                      \
        _Pragma("unroll")                                                      \
        for (int p = 0; p < 2; p++) {                                          \
            int row = warp_n * 32 + p * 16 + b_rowl;                           \
            uint32_t sw = SMEM_SWIZZLE_128B(                                   \
                (uint32_t)(row * 128 + b_colB + (s_) * 32));                   \
            ldsm_x4(fb[2 * p][0], fb[2 * p][1],                                \
                    fb[2 * p + 1][0], fb[2 * p + 1][1], bW + sw);              \
        }                                                                      \
    } while (0)

#define GQ_MMA() do {                                                          \
        _Pragma("unroll")                                                      \
        for (int nb = 0; nb < 4; nb++)                                         \
            _Pragma("unroll")                                                  \
            for (int mb = 0; mb < 2; mb++)                                     \
                mma16816(acc[mb][nb], fa[mb], fb[nb]);                         \
    } while (0)

#define GEMM_MAINLOOP(Aw, Bw)                                                  \
    uint32_t base = (smem_u32(dsm) + 1023u) & ~1023u;                          \
    char* sm = dsm + (base - smem_u32(dsm));                                   \
    float acc[2][4][4];                                                        \
    _Pragma("unroll")                                                          \
    for (int mb = 0; mb < 2; mb++)                                             \
        _Pragma("unroll")                                                      \
        for (int nb = 0; nb < 4; nb++)                                         \
            _Pragma("unroll")                                                  \
            for (int q = 0; q < 4; q++) acc[mb][nb][q] = 0.f;                  \
    const int a_row = lid & 15;                                                \
    const int a_colB = (lid >> 4) * 16;                                        \
    const int b_rowl = ((lid >> 4) << 3) + (lid & 7);                          \
    const int b_colB = ((lid >> 3) & 1) * 16;                                  \
    uint32_t fa[2][4];                                                         \
    uint32_t fb[4][2];                                                         \
    GQ_LOAD_CHUNK(0, 0);                                                       \
    CP_COMMIT();                                                               \
    for (int ch = 0; ch < NCH; ch++) {                                         \
        CP_WAIT(0);                                                            \
        __syncthreads();                                                       \
        uint32_t stg0 = smem_u32(sm + (ch & 1) * STG_BYTES);                   \
        uint32_t aW = stg0;                                                    \
        uint32_t bW = stg0 + 16384;                                            \
        _Pragma("unroll")                                                      \
        for (int s = 0; s < 4; s++) {                                          \
            GQ_LOAD_FRAGS(s);                                                  \
            if (s == 0 && ch + 1 < NCH) {                                      \
                GQ_LOAD_CHUNK(ch + 1, (ch + 1) & 1);                           \
                CP_COMMIT();                                                   \
            }                                                                  \
            GQ_MMA();                                                          \
        }                                                                      \
    }

// ---------------- 1-term GEMM, fp32 epilogue (O projection) ------------------
__global__ __launch_bounds__(512, 1) void gemm_o(
    const __half* __restrict__ Aw, const __half* __restrict__ Bw,
    float* __restrict__ C, int Ncols) {
    extern __shared__ char dsm[];
    const int t = threadIdx.x;
    const int wid = t >> 5;
    const int lid = t & 31;
    const int warp_m = wid & 3;
    const int warp_n = wid >> 2;
    const int rowBase = blockIdx.y * 128;
    const int colBase = blockIdx.x * 128;

    GEMM_MAINLOOP(Aw, Bw)

    const int g = lid >> 2;
    const int q = lid & 3;
#pragma unroll
    for (int mb = 0; mb < 2; mb++) {
#pragma unroll
        for (int nb = 0; nb < 4; nb++) {
            int row = rowBase + warp_m * 32 + mb * 16 + g;
            int col = colBase + warp_n * 32 + nb * 8 + q * 2;
            *reinterpret_cast<float2*>(&C[(size_t)row * Ncols + col]) =
                make_float2(acc[mb][nb][0], acc[mb][nb][1]);
            *reinterpret_cast<float2*>(&C[(size_t)(row + 8) * Ncols + col]) =
                make_float2(acc[mb][nb][2], acc[mb][nb][3]);
        }
    }
}

// ---------------- QKV GEMM (1-term) with fused RoPE + fp16 epilogue ----------
__global__ __launch_bounds__(512, 1) void gemm_qkv(
    const __half* __restrict__ Aw, const __half* __restrict__ Bw,
    __half* __restrict__ qhi,
    __half* __restrict__ khi,
    __half* __restrict__ vhi,
    const float2* __restrict__ ropeTab) {
    extern __shared__ char dsm[];
    const int t = threadIdx.x;
    const int wid = t >> 5;
    const int lid = t & 31;
    const int warp_m = wid & 3;
    const int warp_n = wid >> 2;
    const int rowBase = blockIdx.y * 128;
    const int colBase = blockIdx.x * 128;

    GEMM_MAINLOOP(Aw, Bw)

    const int g2 = lid >> 2;
    const int qd2 = (lid & 3) * 2;

    if (colBase >= DMODEL + DKV) {
        // V: plain fp16, direct from registers
        const int cb = colBase - DMODEL - DKV;
#pragma unroll
        for (int mb = 0; mb < 2; mb++) {
            int r0 = rowBase + warp_m * 32 + mb * 16 + g2;
#pragma unroll
            for (int nb = 0; nb < 4; nb++) {
                int col = cb + warp_n * 32 + nb * 8 + qd2;
                size_t o0 = (size_t)r0 * DKV + col;
                size_t o1 = (size_t)(r0 + 8) * DKV + col;
                *reinterpret_cast<uint32_t*>(vhi + o0) =
                    packhf(acc[mb][nb][0], acc[mb][nb][1]);
                *reinterpret_cast<uint32_t*>(vhi + o1) =
                    packhf(acc[mb][nb][2], acc[mb][nb][3]);
            }
        }
        return;
    }

    // Q/K: bounce accumulators through smem for cross-warp RoPE
    float* stile = reinterpret_cast<float*>(sm);   // [128][128] f32, XOR swizzle
    __syncthreads();   // all warps done with final-chunk fragment reads
#pragma unroll
    for (int mb = 0; mb < 2; mb++) {
#pragma unroll
        for (int nb = 0; nb < 4; nb++) {
            int rl0 = warp_m * 32 + mb * 16 + g2;
            int cw = warp_n * 32 + nb * 8 + qd2;
            uint32_t w0 = rl0 * 128 + (cw ^ ((rl0 & 7) << 3));
            uint32_t w1 = (rl0 + 8) * 128 + (cw ^ (((rl0 + 8) & 7) << 3));
            *reinterpret_cast<float2*>(stile + w0) =
                make_float2(acc[mb][nb][0], acc[mb][nb][1]);
            *reinterpret_cast<float2*>(stile + w1) =
                make_float2(acc[mb][nb][2], acc[mb][nb][3]);
        }
    }
    __syncthreads();

    const bool isQ = colBase < DMODEL;
    const float sc = isQ ? 0.125f : 1.0f;   // 1/sqrt(64) folded into Q
    __half* Hhi = isQ ? qhi : khi;
    const int ncols = isQ ? DMODEL : DKV;
    const int cbase = isQ ? colBase : colBase - DMODEL;

    // 128 rows x 2 heads x 16 j-pairs = 4096 items, 512 threads -> 8 iters
#pragma unroll
    for (int it = 0; it < 8; it++) {
        int i = t + it * 512;
        int j2 = i & 15;
        int head = (i >> 4) & 1;
        int rl = i >> 5;                 // local row 0..127
        int j = 2 * j2;
        int c1 = head * 64 + j;
        uint32_t xr = (uint32_t)((rl & 7) << 3);
        float2 ab0 = *reinterpret_cast<float2*>(stile + rl * 128 + (c1 ^ xr));
        float2 ab1 = *reinterpret_cast<float2*>(stile + rl * 128 + ((c1 + 32) ^ xr));
        int grow = rowBase + rl;
        int srow = grow & (SEQ - 1);
        float2 cs0 = ropeTab[srow * 32 + j];
        float2 cs1 = ropeTab[srow * 32 + j + 1];
        float a0 = ab0.x, a1 = ab0.y, b0 = ab1.x, b1 = ab1.y;
        float q0 = (a0 * cs0.x - b0 * cs0.y) * sc;
        float q1 = (a1 * cs1.x - b1 * cs1.y) * sc;
        float u0 = (b0 * cs0.x + a0 * cs0.y) * sc;
        float u1 = (b1 * cs1.x + a1 * cs1.y) * sc;
        size_t o = (size_t)grow * ncols + cbase + c1;
        *reinterpret_cast<uint32_t*>(Hhi + o) = packhf(q0, q1);
        *reinterpret_cast<uint32_t*>(Hhi + o + 32) = packhf(u0, u1);
    }
}

// ---------------- tensor-core flash attention (causal, GQA) ------------------
// S = 1-term (Q fp16 x K fp16), PV = 1-term (P fp16 x V fp16).
#define KV_STG 16384                  // Khi 8K | Vhi 8K
#define ATTN2_SMEM (16384 + 2 * KV_STG + 1024)

__global__ __launch_bounds__(256, 2) void attn_mma(
    const __half* __restrict__ Qhi,
    const __half* __restrict__ Khi,
    const __half* __restrict__ Vhi,
    __half* __restrict__ Ohi) {
    extern __shared__ char dsm[];
    uint32_t base = (smem_u32(dsm) + 1023u) & ~1023u;
    char* sm = dsm + (base - smem_u32(dsm));
    char* sQhi = sm;            // 16KB

    const int qt = (int)gridDim.x - 1 - (int)blockIdx.x;   // heavy CTAs first
    const int h  = blockIdx.y;
    const int b  = blockIdx.z;
    const int hkv = h >> 2;
    const int t  = threadIdx.x;
    const int wid = t >> 5;
    const int lid = t & 31;
    const int g = lid >> 2;
    const int qd = lid & 3;
    const int q0 = qt * 128;

    const size_t kvbase = ((size_t)b * SEQ) * DKV + (size_t)hkv * HDIM;
    const int ntiles = 2 * qt + 2;

#define LOADKV(kt_, stg_) do {                                                  \
        const int k0_ = (kt_) * 64;                                            \
        uint32_t sb0_ = smem_u32(sm + 16384 + (stg_) * KV_STG);                 \
        _Pragma("unroll")                                                       \
        for (int ii = 0; ii < 2; ii++) {                                        \
            int idx_ = t + ii * 256;                                            \
            int row_ = idx_ >> 3;                                               \
            int ch_ = idx_ & 7;                                                 \
            uint32_t sw_ = SMEM_SWIZZLE_128B((uint32_t)(row_ * 128 + ch_ * 16));\
            size_t gl_ = kvbase + (size_t)(k0_ + row_) * DKV + ch_ * 8;         \
            cp16(sb0_ + sw_, Khi + gl_);                                        \
            cp16(sb0_ + 8192 + sw_, Vhi + gl_);                                 \
        }                                                                       \
    } while (0)

    // group A: Q tile via cp.async
    {
        const __half* Qh = Qhi + ((size_t)(b * SEQ + q0)) * DMODEL + h * HDIM;
#pragma unroll
        for (int ii = 0; ii < 4; ii++) {
            int idx = t + ii * 256;        // 0..1023
            int row = idx >> 3;
            int ch = idx & 7;
            uint32_t sw = SMEM_SWIZZLE_128B((uint32_t)(row * 128 + ch * 16));
            size_t gl = (size_t)row * DMODEL + ch * 8;
            cp16(smem_u32(sQhi) + sw, Qh + gl);
        }
        CP_COMMIT();
    }
    // group B: KV tile 0
    LOADKV(0, 0);
    CP_COMMIT();

    CP_WAIT(1);        // Q tile complete
    __syncthreads();

    // ---- Q fragments in registers
    uint32_t qh[4][4];
    {
        int arow = wid * 16 + (lid & 15);
        int acolB = (lid >> 4) * 16;
#pragma unroll
        for (int s = 0; s < 4; s++) {
            uint32_t sw = SMEM_SWIZZLE_128B((uint32_t)(arow * 128 + acolB + s * 32));
            ldsm_x4(qh[s][0], qh[s][1], qh[s][2], qh[s][3], smem_u32(sQhi) + sw);
        }
    }

    float o[8][4];
#pragma unroll
    for (int nb = 0; nb < 8; nb++)
#pragma unroll
        for (int q = 0; q < 4; q++) o[nb][q] = 0.f;
    float m0 = -1e30f, m1 = -1e30f, l0 = 0.f, l1 = 0.f;

    for (int kt = 0; kt < ntiles; kt++) {
        const int k0 = kt * 64;
        if (kt + 1 < ntiles) {
            LOADKV(kt + 1, (kt + 1) & 1);
            CP_COMMIT();
            CP_WAIT(1);
        } else {
            CP_WAIT(0);
        }
        __syncthreads();

        uint32_t kvb = smem_u32(sm + 16384 + (kt & 1) * KV_STG);
        uint32_t sKhi_ = kvb;
        uint32_t sVhi_ = kvb + 8192;

        // ---- S = Q K^T (1-term fp16)
        float sacc[8][4];
#pragma unroll
        for (int nb = 0; nb < 8; nb++)
#pragma unroll
            for (int q = 0; q < 4; q++) sacc[nb][q] = 0.f;

        {
            int brow = ((lid >> 4) << 3) + (lid & 7);
            int bcolB = ((lid >> 3) & 1) * 16;
#pragma unroll
            for (int s = 0; s < 4; s++) {
                uint32_t kh[8][2];
#pragma unroll
                for (int p = 0; p < 4; p++) {
                    uint32_t sw = SMEM_SWIZZLE_128B(
                        (uint32_t)((p * 16 + brow) * 128 + bcolB + s * 32));
                    ldsm_x4(kh[2 * p][0], kh[2 * p][1], kh[2 * p + 1][0],
                            kh[2 * p + 1][1], sKhi_ + sw);
                }
#pragma unroll
                for (int nb = 0; nb < 8; nb++)
                    mma16816(sacc[nb], qh[s], kh[nb]);
            }
        }

        // ---- causal mask (only diagonal tiles)
        if (kt >= 2 * qt) {
            int rowa = q0 + wid * 16 + g;
#pragma unroll
            for (int nb = 0; nb < 8; nb++) {
                int col = k0 + nb * 8 + qd * 2;
                if (col > rowa)     sacc[nb][0] = -1e30f;
                if (col + 1 > rowa) sacc[nb][1] = -1e30f;
                if (col > rowa + 8)     sacc[nb][2] = -1e30f;
                if (col + 1 > rowa + 8) sacc[nb][3] = -1e30f;
            }
        }

        // ---- online softmax
        {
            float mx0 = -1e30f, mx1 = -1e30f;
#pragma unroll
            for (int nb = 0; nb < 8; nb++) {
                mx0 = fmaxf(mx0, fmaxf(sacc[nb][0], sacc[nb][1]));
                mx1 = fmaxf(mx1, fmaxf(sacc[nb][2], sacc[nb][3]));
            }
            mx0 = fmaxf(mx0, __shfl_xor_sync(0xffffffff, mx0, 1));
            mx0 = fmaxf(mx0, __shfl_xor_sync(0xffffffff, mx0, 2));
            mx1 = fmaxf(mx1, __shfl_xor_sync(0xffffffff, mx1, 1));
            mx1 = fmaxf(mx1, __shfl_xor_sync(0xffffffff, mx1, 2));
            float mn0 = fmaxf(m0, mx0), mn1 = fmaxf(m1, mx1);
            float al0 = __expf(m0 - mn0), al1 = __expf(m1 - mn1);
            m0 = mn0; m1 = mn1;
            l0 *= al0; l1 *= al1;
            float la0 = 0.f, la1 = 0.f;
#pragma unroll
            for (int nb = 0; nb < 8; nb++) {
                sacc[nb][0] = __expf(sacc[nb][0] - mn0);
                sacc[nb][1] = __expf(sacc[nb][1] - mn0);
                sacc[nb][2] = __expf(sacc[nb][2] - mn1);
                sacc[nb][3] = __expf(sacc[nb][3] - mn1);
                la0 += sacc[nb][0] + sacc[nb][1];
                la1 += sacc[nb][2] + sacc[nb][3];
                o[nb][0] *= al0; o[nb][1] *= al0;
                o[nb][2] *= al1; o[nb][3] *= al1;
            }
            l0 += la0; l1 += la1;
        }

        // ---- pack P as fp16 A-fragments
        uint32_t ph[4][4];
#pragma unroll
        for (int j = 0; j < 4; j++) {
            float* c = sacc[2 * j];
            float* d = sacc[2 * j + 1];
            ph[j][0] = packhf(c[0], c[1]);
            ph[j][1] = packhf(c[2], c[3]);
            ph[j][2] = packhf(d[0], d[1]);
            ph[j][3] = packhf(d[2], d[3]);
        }

        // ---- O += P V (1-term), V via ldmatrix.trans
        {
            int vrow = (lid & 15);
            int vcolB = (lid >> 4) * 16;
#pragma unroll
            for (int j = 0; j < 4; j++) {
                uint32_t vh[8][2];
#pragma unroll
                for (int dj = 0; dj < 4; dj++) {
                    uint32_t sw = SMEM_SWIZZLE_128B(
                        (uint32_t)((j * 16 + vrow) * 128 + dj * 32 + vcolB));
                    ldsm_x4_t(vh[2 * dj][0], vh[2 * dj][1], vh[2 * dj + 1][0],
                              vh[2 * dj + 1][1], sVhi_ + sw);
                }
#pragma unroll
                for (int nb = 0; nb < 8; nb++)
                    mma16816(o[nb], ph[j], vh[nb]);
            }
        }
        __syncthreads();
    }
#undef LOADKV

    // ---- finalize: normalize, write fp16
    l0 += __shfl_xor_sync(0xffffffff, l0, 1);
    l0 += __shfl_xor_sync(0xffffffff, l0, 2);
    l1 += __shfl_xor_sync(0xffffffff, l1, 1);
    l1 += __shfl_xor_sync(0xffffffff, l1, 2);
    float inv0 = 1.0f / l0, inv1 = 1.0f / l1;

    int rowa = q0 + wid * 16 + g;
    size_t oa = ((size_t)(b * SEQ + rowa)) * DMODEL + h * HDIM;
    size_t ob = ((size_t)(b * SEQ + rowa + 8)) * DMODEL + h * HDIM;
#pragma unroll
    for (int nb = 0; nb < 8; nb++) {
        int col = nb * 8 + qd * 2;
        *reinterpret_cast<uint32_t*>(Ohi + oa + col) =
            packhf(o[nb][0] * inv0, o[nb][1] * inv0);
        *reinterpret_cast<uint32_t*>(Ohi + ob + col) =
            packhf(o[nb][2] * inv1, o[nb][3] * inv1);
    }
}

// ---------------- launch ------------------------------------------------------
extern "C" void kernel_launch(void* const* d_in, const int* in_sizes, int n_in,
                              void* d_out, int out_size) {
    (void)in_sizes; (void)n_in; (void)out_size;
    const float* x  = (const float*)d_in[0];
    const float* Wq = (const float*)d_in[1];
    const float* Wk = (const float*)d_in[2];
    const float* Wv = (const float*)d_in[3];
    const float* Wo = (const float*)d_in[4];
    const int* poff = (const int*)d_in[5];
    float* out = (float*)d_out;

    __half *xhi, *qhi, *khi, *vhi, *wqkv, *wo;
    float2* rtab;
    cudaGetSymbolAddress((void**)&xhi, g_xhi);
    cudaGetSymbolAddress((void**)&qhi, g_Qhi);
    cudaGetSymbolAddress((void**)&khi, g_Khi);
    cudaGetSymbolAddress((void**)&vhi, g_Vhi);
    cudaGetSymbolAddress((void**)&wqkv, g_wqkv);
    cudaGetSymbolAddress((void**)&wo, g_wo);
    cudaGetSymbolAddress((void**)&rtab, g_rope);

    cudaFuncSetAttribute(gemm_o, cudaFuncAttributeMaxDynamicSharedMemorySize,
                         GEMM_SMEM_BYTES);
    cudaFuncSetAttribute(gemm_qkv, cudaFuncAttributeMaxDynamicSharedMemorySize,
                         GEMM_SMEM_BYTES);
    cudaFuncSetAttribute(attn_mma, cudaFuncAttributeMaxDynamicSharedMemorySize,
                         ATTN2_SMEM);

    // fused prep: x convert + weight transposes + rope table (one launch)
    prep_kernel<<<dim3(128, 32, 6), dim3(32, 8)>>>(
        x, Wq, Wk, Wv, Wo, poff, xhi, wqkv, wo, rtab);

    // fused QKV projection (1-term) + RoPE + fp16 epilogue (512 thr)
    gemm_qkv<<<dim3(NQKV / 128, ROWS / 128), 512, GEMM_SMEM_BYTES>>>(
        xhi, wqkv, qhi, khi, vhi, rtab);

    // attention (1-term S & PV) -> writes fp16 into xhi
    attn_mma<<<dim3(SEQ / 128, NHEADS, BATCH), 256, ATTN2_SMEM>>>(
        qhi, khi, vhi, xhi);

    // O projection (1-term, 512 thr)
    gemm_o<<<dim3(DMODEL / 128, ROWS / 128), 512, GEMM_SMEM_BYTES>>>(
        xhi, wo, out, DMODEL);
}